// round 11
// baseline (speedup 1.0000x reference)
#include <cuda_runtime.h>
#include <cuda_bf16.h>
#include <cstdint>
#include <math.h>

// Problem dims (fixed)
#define NB   8
#define NS   1024
#define NH   16
#define NDK  64
#define FDEC 1024
#define FD   16
#define KINR 784
#define KP   1024
#define KPD  800          // dense GEMM K padded to 25*32
#define MROWS (NB*NS)     // 8192

// ---------------- scratch (static __device__, no allocation) ----------------
__device__ float g_xcat[MROWS * KPD];    // concat input, tf32-rounded, K=800
__device__ float g_x   [MROWS * FDEC];   // dense output (residual, fp32)
__device__ float g_xn  [MROWS * FDEC];   // LN output, tf32-rounded
__device__ float g_q   [MROWS * FDEC];
__device__ float g_k   [MROWS * FDEC];
__device__ float g_v   [MROWS * FDEC];
__device__ float g_o   [MROWS * FDEC];   // attention out, fp32
__device__ float g_wd  [FDEC * KPD];     // dense weight rounded/padded, K=800
__device__ float g_wqr [FDEC * KP];
__device__ float g_wkr [FDEC * KP];
__device__ float g_wvr [FDEC * KP];
__device__ float g_wc  [FD * FDEC];      // dcw @ wo  [16][1024]
__device__ float g_cadd[FD];             // dcw . bo + dec_b

// ---------------- PTX helpers ------------------------------------------------
__device__ __forceinline__ uint32_t smem_u32(const void* p) {
    uint32_t a;
    asm("{ .reg .u64 t; cvta.to.shared.u64 t, %1; cvt.u32.u64 %0, t; }" : "=r"(a) : "l"(p));
    return a;
}

#define LDSM4(R, A) \
    asm volatile("ldmatrix.sync.aligned.m8n8.x4.shared.b16 {%0,%1,%2,%3}, [%4];" \
        : "=r"((R)[0]), "=r"((R)[1]), "=r"((R)[2]), "=r"((R)[3]) : "r"(A))

#define MMA_TF32(C, A, B0, B1) \
    asm volatile("mma.sync.aligned.m16n8k8.row.col.f32.tf32.tf32.f32 " \
        "{%0,%1,%2,%3},{%4,%5,%6,%7},{%8,%9},{%0,%1,%2,%3};" \
        : "+f"((C)[0]), "+f"((C)[1]), "+f"((C)[2]), "+f"((C)[3]) \
        : "r"((A)[0]), "r"((A)[1]), "r"((A)[2]), "r"((A)[3]), "r"(B0), "r"(B1))

__device__ __forceinline__ uint32_t to_tf32(float f) {
    uint32_t r;
    asm("cvt.rna.tf32.f32 %0, %1;" : "=r"(r) : "f"(f));
    return r;
}
__device__ __forceinline__ float tf32r(float f) {
    return __uint_as_float(to_tf32(f));
}

__device__ __forceinline__ void cpa16(uint32_t dst, const void* src) {
    asm volatile("cp.async.cg.shared.global [%0], [%1], 16;" :: "r"(dst), "l"(src));
}
#define CP_COMMIT() asm volatile("cp.async.commit_group;" ::: "memory")
#define CP_WAIT(n)  asm volatile("cp.async.wait_group %0;" :: "n"(n) : "memory")

// ---------------- producers --------------------------------------------------
__global__ void __launch_bounds__(256) concat_k(
    const float* __restrict__ r, const float* __restrict__ z,
    float* __restrict__ xcat)
{
    int idx = blockIdx.x * 256 + threadIdx.x;
    if (idx >= MROWS * KPD) return;
    int m = idx / KPD, f = idx - m * KPD;
    float v = (f < 16) ? r[m * 16 + f]
            : (f < KINR) ? z[(m >> 10) * 768 + (f - 16)] : 0.f;
    xcat[idx] = tf32r(v);
}

// weight round + pad: w [1024, Ksrc] -> tf32-rounded [1024, Kdst]
__global__ void __launch_bounds__(256) roundpad_k(
    const float* __restrict__ w, int Ksrc, int Kdst, float* __restrict__ dst)
{
    int idx = blockIdx.x * 256 + threadIdx.x;
    if (idx >= FDEC * Kdst) return;
    int n = idx / Kdst, k = idx - n * Kdst;
    dst[idx] = (k < Ksrc) ? tf32r(w[n * Ksrc + k]) : 0.f;
}

// wc[n][j] = sum_k dcw[n][k] * wo[k][j]   (16 x 1024, K=1024)
__global__ void __launch_bounds__(256) wcomb_k(
    const float* __restrict__ dcw, const float* __restrict__ wo,
    float* __restrict__ wc)
{
    const int k0 = blockIdx.x * 64;                // 16 blocks
    const int n = threadIdx.x >> 4;                // 0..15
    const int kq = (threadIdx.x & 15) * 4;         // 0..60
    float acc[4] = {0.f, 0.f, 0.f, 0.f};
    for (int j = 0; j < FDEC; j++) {
        float d = dcw[n * FDEC + j];
        float4 w4 = *(const float4*)(wo + (size_t)j * FDEC + k0 + kq);
        acc[0] += d * w4.x; acc[1] += d * w4.y;
        acc[2] += d * w4.z; acc[3] += d * w4.w;
    }
    *(float4*)(wc + n * FDEC + k0 + kq) = make_float4(acc[0], acc[1], acc[2], acc[3]);
}

// cadd[n] = dec_b[n] + sum_k dcw[n][k] * bo[k]
__global__ void __launch_bounds__(512) cvec_k(
    const float* __restrict__ dcw, const float* __restrict__ bo,
    const float* __restrict__ dcb, float* __restrict__ cadd)
{
    const int n = threadIdx.x >> 5, lane = threadIdx.x & 31;
    float sum = 0.f;
    #pragma unroll
    for (int i = 0; i < 8; i++) {
        float4 a = ((const float4*)(dcw + n * FDEC))[lane + i * 32];
        float4 b = ((const float4*)bo)[lane + i * 32];
        sum += a.x * b.x + a.y * b.y + a.z * b.z + a.w * b.w;
    }
    #pragma unroll
    for (int o = 16; o; o >>= 1) sum += __shfl_xor_sync(0xffffffffu, sum, o);
    if (lane == 0) cadd[n] = sum + dcb[n];
}

// ---------------- LayerNorm (fp32 in, tf32-rounded out) ----------------------
__device__ __forceinline__ float blockReduce(float val, float* sh)
{
    __syncthreads();
    int lane = threadIdx.x & 31, wid = threadIdx.x >> 5;
    #pragma unroll
    for (int o = 16; o; o >>= 1) val += __shfl_xor_sync(0xffffffffu, val, o);
    if (lane == 0) sh[wid] = val;
    __syncthreads();
    if (wid == 0) {
        val = (lane < 8) ? sh[lane] : 0.f;
        #pragma unroll
        for (int o = 4; o; o >>= 1) val += __shfl_xor_sync(0xffffffffu, val, o);
        if (lane == 0) sh[0] = val;
    }
    __syncthreads();
    return sh[0];
}

__global__ void __launch_bounds__(256) ln_k(
    const float* __restrict__ x, const float* __restrict__ g,
    const float* __restrict__ beta, float* __restrict__ xn)
{
    __shared__ float red[32];
    int row = blockIdx.x;
    float4 v = ((const float4*)(x + (size_t)row * 1024))[threadIdx.x];
    float s = blockReduce(v.x + v.y + v.z + v.w, red);
    float mean = s * (1.0f / 1024.0f);
    float dx = v.x - mean, dy = v.y - mean, dz = v.z - mean, dw = v.w - mean;
    float s2 = blockReduce(dx*dx + dy*dy + dz*dz + dw*dw, red);
    float inv = rsqrtf(s2 * (1.0f / 1024.0f) + 1e-6f);
    float4 gg = ((const float4*)g)[threadIdx.x];
    float4 bb = ((const float4*)beta)[threadIdx.x];
    float4 o;
    o.x = tf32r(gg.x * dx * inv + bb.x);
    o.y = tf32r(gg.y * dy * inv + bb.y);
    o.z = tf32r(gg.z * dz * inv + bb.z);
    o.w = tf32r(gg.w * dw * inv + bb.w);
    ((float4*)(xn + (size_t)row * 1024))[threadIdx.x] = o;
}

// ---------------- tf32 mma GEMM core (ldmatrix fragments) --------------------
// Block 128x128, 256 thr (8 warps, 4m x 2n), warp tile 32x64, K-tile 32,
// 3-stage cp.async. KROW = global row stride (floats), KITER = K/32.
// MODE 0: plain store, MODE 1: qkv scatter [B,H,S,DK].
#define GSTR  36
#define TILE_BYTES (128 * GSTR * 4)
#define STAGE_B (2 * TILE_BYTES)
#define GEMM_SMEM (3 * STAGE_B)

template<int MODE, int KROW, int KITER>
__device__ __forceinline__ void gemm_core(
    const float* __restrict__ A, const float* __restrict__ Bw,
    const float* __restrict__ bias, float* __restrict__ C,
    char* sm, int bm, int bn)
{
    const uint32_t sbase = smem_u32(sm);
    const int tid = threadIdx.x, lane = tid & 31, wid = tid >> 5;
    const int g4 = lane >> 2, t4 = lane & 3;
    const int wm = (wid & 3) * 32, wn = (wid >> 2) * 64;

    float acc[2][8][4];
    #pragma unroll
    for (int a = 0; a < 2; a++)
        #pragma unroll
        for (int b = 0; b < 8; b++)
            #pragma unroll
            for (int c = 0; c < 4; c++) acc[a][b][c] = 0.f;

    const uint32_t aoff =
        ((uint32_t)(wm + (lane & 7) + ((lane >> 3) & 1) * 8) * GSTR
         + ((lane >> 4) << 2)) * 4;
    const uint32_t boff =
        ((uint32_t)(wn + (lane & 7)) * GSTR + ((lane >> 3) & 3) * 4) * 4;

    auto load_stage = [&](int slot, int k0) {
        const uint32_t sa = sbase + slot * STAGE_B;
        #pragma unroll
        for (int c = 0; c < 4; c++) {
            int chunk = tid + c * 256;
            int row = chunk >> 3, seg = chunk & 7;
            cpa16(sa + row * (GSTR*4) + seg * 16,
                  A + (size_t)(bm + row) * KROW + k0 + seg * 4);
        }
        const uint32_t sb = sa + TILE_BYTES;
        #pragma unroll
        for (int c = 0; c < 4; c++) {
            int chunk = tid + c * 256;
            int row = chunk >> 3, seg = chunk & 7;
            cpa16(sb + row * (GSTR*4) + seg * 16,
                  Bw + (size_t)(bn + row) * KROW + k0 + seg * 4);
        }
    };

    load_stage(0, 0);  CP_COMMIT();
    load_stage(1, 32); CP_COMMIT();

    for (int i = 0; i < KITER; i++) {
        if (i < KITER - 1) { CP_WAIT(1); } else { CP_WAIT(0); }
        __syncthreads();
        if (i + 2 < KITER) { load_stage((i + 2) % 3, (i + 2) * 32); CP_COMMIT(); }

        const uint32_t As = sbase + (i % 3) * STAGE_B;
        const uint32_t Bs = As + TILE_BYTES;

        uint32_t a[4][2][4];
        #pragma unroll
        for (int kk = 0; kk < 4; kk++)
            #pragma unroll
            for (int am = 0; am < 2; am++)
                LDSM4(a[kk][am], As + aoff + am * (16 * GSTR * 4) + kk * 32);

        #pragma unroll
        for (int nt = 0; nt < 8; nt++) {
            uint32_t b01[4], b23[4];
            const uint32_t bb = Bs + boff + nt * (8 * GSTR * 4);
            LDSM4(b01, bb);
            LDSM4(b23, bb + 64);
            MMA_TF32(acc[0][nt], a[0][0], b01[0], b01[1]);
            MMA_TF32(acc[1][nt], a[0][1], b01[0], b01[1]);
            MMA_TF32(acc[0][nt], a[1][0], b01[2], b01[3]);
            MMA_TF32(acc[1][nt], a[1][1], b01[2], b01[3]);
            MMA_TF32(acc[0][nt], a[2][0], b23[0], b23[1]);
            MMA_TF32(acc[1][nt], a[2][1], b23[0], b23[1]);
            MMA_TF32(acc[0][nt], a[3][0], b23[2], b23[3]);
            MMA_TF32(acc[1][nt], a[3][1], b23[2], b23[3]);
        }
    }

    #pragma unroll
    for (int am = 0; am < 2; am++) {
        #pragma unroll
        for (int nt = 0; nt < 8; nt++) {
            int mrow = bm + wm + am * 16 + g4;
            int ncol = bn + wn + nt * 8 + t4 * 2;
            float b0 = bias[ncol], b1 = bias[ncol + 1];
            #pragma unroll
            for (int r = 0; r < 2; r++) {
                int m = mrow + r * 8;
                float v0 = acc[am][nt][r * 2]     + b0;
                float v1 = acc[am][nt][r * 2 + 1] + b1;
                if (MODE == 0) {
                    *(float2*)&C[(size_t)m * 1024 + ncol] = make_float2(v0, v1);
                } else {
                    int bb = m >> 10, s = m & 1023, h = ncol >> 6, d = ncol & 63;
                    *(float2*)&C[(size_t)(((bb << 4) + h) * 1024 + s) * 64 + d] =
                        make_float2(v0, v1);
                }
            }
        }
    }
}

// dense: K=800
__global__ void __launch_bounds__(256) gemm_dense(
    const float* __restrict__ A, const float* __restrict__ Bw,
    const float* __restrict__ bias, float* __restrict__ C)
{
    extern __shared__ char sm[];
    gemm_core<0, KPD, KPD/32>(A, Bw, bias, C, sm, blockIdx.y * 128, blockIdx.x * 128);
}

// merged QKV: blockIdx.z selects weight/bias/output
__global__ void __launch_bounds__(256) gemm_qkv(
    const float* __restrict__ A,
    const float* __restrict__ W0, const float* __restrict__ W1, const float* __restrict__ W2,
    const float* __restrict__ b0, const float* __restrict__ b1, const float* __restrict__ b2,
    float* __restrict__ C0, float* __restrict__ C1, float* __restrict__ C2)
{
    extern __shared__ char sm[];
    const int zz = blockIdx.z;
    const float* W = (zz == 0) ? W0 : (zz == 1) ? W1 : W2;
    const float* bs = (zz == 0) ? b0 : (zz == 1) ? b1 : b2;
    float* C = (zz == 0) ? C0 : (zz == 1) ? C1 : C2;
    gemm_core<1, KP, KP/32>(A, W, bs, C, sm, blockIdx.y * 128, blockIdx.x * 128);
}

// ---------------- fused decode: out = x.dw + o.wc + cadd, transposed ---------
__global__ void __launch_bounds__(512) dec2_k(
    const float* __restrict__ x, const float* __restrict__ o,
    const float* __restrict__ dw, const float* __restrict__ wc,
    const float* __restrict__ cadd, float* __restrict__ out)
{
    const int m = blockIdx.x;
    const int b = m >> 10, s = m & 1023;
    const int n = threadIdx.x >> 5;
    const int lane = threadIdx.x & 31;
    const float4* xr = (const float4*)(x  + (size_t)m * FDEC);
    const float4* orr = (const float4*)(o + (size_t)m * FDEC);
    const float4* wr = (const float4*)(dw + (size_t)n * FDEC);
    const float4* cr = (const float4*)(wc + (size_t)n * FDEC);
    float sum = 0.f;
    #pragma unroll
    for (int i = 0; i < 8; i++) {
        float4 a = xr[lane + i * 32];
        float4 w = wr[lane + i * 32];
        float4 oo = orr[lane + i * 32];
        float4 c = cr[lane + i * 32];
        sum += a.x * w.x + a.y * w.y + a.z * w.z + a.w * w.w;
        sum += oo.x * c.x + oo.y * c.y + oo.z * c.z + oo.w * c.w;
    }
    #pragma unroll
    for (int oo = 16; oo; oo >>= 1) sum += __shfl_xor_sync(0xffffffffu, sum, oo);
    if (lane == 0)
        out[(size_t)(b * FD + n) * NS + s] = sum + cadd[n];
}

// ---------------- tf32 mma flash attention with ALiBi ------------------------
#define ASTR 68
#define ATTN_SMEM (3 * 64 * ASTR * (int)sizeof(float))

__global__ void __launch_bounds__(128) attn_tc(
    const float* __restrict__ q, const float* __restrict__ k,
    const float* __restrict__ v, float* __restrict__ o)
{
    extern __shared__ float smf[];
    float* Ks = smf;
    float* Vs = Ks + 64 * ASTR;
    float* Ps = Vs + 64 * ASTR;

    const int qc = blockIdx.x, h = blockIdx.y, b = blockIdx.z;
    const int tid = threadIdx.x, lane = tid & 31, w = tid >> 5;
    const int g4 = lane >> 2, t4 = lane & 3;

    const size_t head = (size_t)(b * NH + h) * NS * NDK;
    const float* qb = q + head;
    const float* kb = k + head;
    const float* vb = v + head;

    uint32_t qa[8][4];
    {
        const int r0 = qc * 64 + w * 16 + g4;
        #pragma unroll
        for (int kk = 0; kk < 8; kk++) {
            int c0 = kk * 8 + t4;
            qa[kk][0] = to_tf32(qb[(size_t)r0 * 64 + c0] * 0.125f);
            qa[kk][1] = to_tf32(qb[(size_t)(r0 + 8) * 64 + c0] * 0.125f);
            qa[kk][2] = to_tf32(qb[(size_t)r0 * 64 + c0 + 4] * 0.125f);
            qa[kk][3] = to_tf32(qb[(size_t)(r0 + 8) * 64 + c0 + 4] * 0.125f);
        }
    }

    const float slope = exp2f(-0.5f * (float)(h + 1));
    float oacc[8][4];
    #pragma unroll
    for (int dt = 0; dt < 8; dt++)
        #pragma unroll
        for (int c = 0; c < 4; c++) oacc[dt][c] = 0.f;
    float mrow[2] = { -1e30f, -1e30f };
    float lrow[2] = { 0.f, 0.f };

    const int lrow_ld = tid >> 1, lcol0 = (tid & 1) * 32;

    for (int kc = 0; kc <= qc; kc++) {
        {
            const float* ksrc = kb + (size_t)(kc * 64 + lrow_ld) * 64 + lcol0;
            const float* vsrc = vb + (size_t)(kc * 64 + lrow_ld) * 64 + lcol0;
            float* kd = Ks + lrow_ld * ASTR + lcol0;
            #pragma unroll
            for (int c = 0; c < 32; c += 4) {
                float4 t = *(const float4*)(ksrc + c);
                *(float4*)(kd + c) = t;
                float4 tv = *(const float4*)(vsrc + c);
                Vs[(lcol0 + c + 0) * ASTR + lrow_ld] = tv.x;
                Vs[(lcol0 + c + 1) * ASTR + lrow_ld] = tv.y;
                Vs[(lcol0 + c + 2) * ASTR + lrow_ld] = tv.z;
                Vs[(lcol0 + c + 3) * ASTR + lrow_ld] = tv.w;
            }
        }
        __syncthreads();

        float sc[8][4];
        #pragma unroll
        for (int nt = 0; nt < 8; nt++) {
            sc[nt][0] = sc[nt][1] = sc[nt][2] = sc[nt][3] = 0.f;
            #pragma unroll
            for (int kk = 0; kk < 8; kk++) {
                const float* kp = &Ks[(nt * 8 + g4) * ASTR + kk * 8 + t4];
                uint32_t b0 = to_tf32(kp[0]);
                uint32_t b1 = to_tf32(kp[4]);
                MMA_TF32(sc[nt], qa[kk], b0, b1);
            }
        }

        const bool diag = (kc == qc);
        #pragma unroll
        for (int half = 0; half < 2; half++) {
            const int wr = w * 16 + g4 + half * 8;
            const int ig = qc * 64 + wr;
            float mx = -1e30f;
            #pragma unroll
            for (int nt = 0; nt < 8; nt++) {
                #pragma unroll
                for (int e = 0; e < 2; e++) {
                    int jl = nt * 8 + t4 * 2 + e;
                    int jg = kc * 64 + jl;
                    float val = sc[nt][half * 2 + e] + slope * (float)jg;
                    if (diag && jg > ig) val -= 1e9f;
                    sc[nt][half * 2 + e] = val;
                    mx = fmaxf(mx, val);
                }
            }
            mx = fmaxf(mx, __shfl_xor_sync(0xffffffffu, mx, 1));
            mx = fmaxf(mx, __shfl_xor_sync(0xffffffffu, mx, 2));
            float mnew = fmaxf(mrow[half], mx);
            float corr = __expf(mrow[half] - mnew);
            mrow[half] = mnew;
            float rs = 0.f;
            #pragma unroll
            for (int nt = 0; nt < 8; nt++) {
                #pragma unroll
                for (int e = 0; e < 2; e++) {
                    float p = __expf(sc[nt][half * 2 + e] - mnew);
                    rs += p;
                    Ps[wr * ASTR + nt * 8 + t4 * 2 + e] = p;
                }
            }
            rs += __shfl_xor_sync(0xffffffffu, rs, 1);
            rs += __shfl_xor_sync(0xffffffffu, rs, 2);
            lrow[half] = lrow[half] * corr + rs;
            #pragma unroll
            for (int dt = 0; dt < 8; dt++) {
                oacc[dt][half * 2]     *= corr;
                oacc[dt][half * 2 + 1] *= corr;
            }
        }
        __syncwarp();

        #pragma unroll
        for (int kk = 0; kk < 8; kk++) {
            uint32_t pa[4];
            const int pr = w * 16 + g4;
            pa[0] = to_tf32(Ps[pr * ASTR + kk * 8 + t4]);
            pa[1] = to_tf32(Ps[(pr + 8) * ASTR + kk * 8 + t4]);
            pa[2] = to_tf32(Ps[pr * ASTR + kk * 8 + t4 + 4]);
            pa[3] = to_tf32(Ps[(pr + 8) * ASTR + kk * 8 + t4 + 4]);
            #pragma unroll
            for (int dt = 0; dt < 8; dt++) {
                const float* vp = &Vs[(dt * 8 + g4) * ASTR + kk * 8 + t4];
                uint32_t b0 = to_tf32(vp[0]);
                uint32_t b1 = to_tf32(vp[4]);
                MMA_TF32(oacc[dt], pa, b0, b1);
            }
        }
        __syncthreads();
    }

    #pragma unroll
    for (int half = 0; half < 2; half++) {
        const int sg = qc * 64 + w * 16 + g4 + half * 8;
        const float inv = 1.0f / lrow[half];
        const size_t base = (size_t)(b * NS + sg) * (NH * NDK) + h * NDK;
        #pragma unroll
        for (int dt = 0; dt < 8; dt++) {
            int d = dt * 8 + t4 * 2;
            float v0 = oacc[dt][half * 2]     * inv;
            float v1 = oacc[dt][half * 2 + 1] * inv;
            *(float2*)&o[base + d] = make_float2(v0, v1);
        }
    }
}

// ---------------- launcher ----------------------------------------------------
extern "C" void kernel_launch(void* const* d_in, const int* in_sizes, int n_in,
                              void* d_out, int out_size)
{
    const float* z   = (const float*)d_in[0];
    const float* r   = (const float*)d_in[1];
    const float* dwn = (const float*)d_in[2];
    const float* dbn = (const float*)d_in[3];
    const float* lng = (const float*)d_in[4];
    const float* lnb = (const float*)d_in[5];
    const float* wq  = (const float*)d_in[6];
    const float* bq  = (const float*)d_in[7];
    const float* wk  = (const float*)d_in[8];
    const float* bk  = (const float*)d_in[9];
    const float* wv  = (const float*)d_in[10];
    const float* bv  = (const float*)d_in[11];
    const float* wo  = (const float*)d_in[12];
    const float* bo  = (const float*)d_in[13];
    const float* dcw = (const float*)d_in[14];
    const float* dcb = (const float*)d_in[15];
    float* out = (float*)d_out;

    float *xcat, *x, *xn, *q, *k, *v, *o;
    float *wd, *wqr, *wkr, *wvr, *wc, *cadd;
    cudaGetSymbolAddress((void**)&xcat, g_xcat);
    cudaGetSymbolAddress((void**)&x,    g_x);
    cudaGetSymbolAddress((void**)&xn,   g_xn);
    cudaGetSymbolAddress((void**)&q,    g_q);
    cudaGetSymbolAddress((void**)&k,    g_k);
    cudaGetSymbolAddress((void**)&v,    g_v);
    cudaGetSymbolAddress((void**)&o,    g_o);
    cudaGetSymbolAddress((void**)&wd,   g_wd);
    cudaGetSymbolAddress((void**)&wqr,  g_wqr);
    cudaGetSymbolAddress((void**)&wkr,  g_wkr);
    cudaGetSymbolAddress((void**)&wvr,  g_wvr);
    cudaGetSymbolAddress((void**)&wc,   g_wc);
    cudaGetSymbolAddress((void**)&cadd, g_cadd);

    cudaFuncSetAttribute(gemm_dense, cudaFuncAttributeMaxDynamicSharedMemorySize, GEMM_SMEM);
    cudaFuncSetAttribute(gemm_qkv,   cudaFuncAttributeMaxDynamicSharedMemorySize, GEMM_SMEM);
    cudaFuncSetAttribute(attn_tc,    cudaFuncAttributeMaxDynamicSharedMemorySize, ATTN_SMEM);

    // producers
    concat_k<<<(MROWS * KPD + 255) / 256, 256>>>(r, z, xcat);
    roundpad_k<<<(FDEC * KPD + 255) / 256, 256>>>(dwn, KINR, KPD, wd);
    roundpad_k<<<(FDEC * KP + 255) / 256, 256>>>(wq, FDEC, KP, wqr);
    roundpad_k<<<(FDEC * KP + 255) / 256, 256>>>(wk, FDEC, KP, wkr);
    roundpad_k<<<(FDEC * KP + 255) / 256, 256>>>(wv, FDEC, KP, wvr);
    wcomb_k<<<16, 256>>>(dcw, wo, wc);
    cvec_k<<<1, 512>>>(dcw, bo, dcb, cadd);

    // dense (K=800)
    gemm_dense<<<dim3(8, 64), 256, GEMM_SMEM>>>(xcat, wd, dbn, x);
    // LN
    ln_k<<<MROWS, 256>>>(x, lng, lnb, xn);
    // merged QKV
    gemm_qkv<<<dim3(8, 64, 3), 256, GEMM_SMEM>>>(xn, wqr, wkr, wvr,
                                                 bq, bk, bv, q, k, v);
    // attention
    attn_tc<<<dim3(NS / 64, NH, NB), 128, ATTN_SMEM>>>(q, k, v, o);
    // fused decode: out = x.dw + o.(dcw@wo) + (dcw.bo + dec_b), transposed
    dec2_k<<<MROWS, 512>>>(x, o, dcw, wc, cadd, out);
}

// round 12
// speedup vs baseline: 1.0397x; 1.0397x over previous
#include <cuda_runtime.h>
#include <cuda_bf16.h>
#include <cstdint>
#include <math.h>

// Problem dims (fixed)
#define NB   8
#define NS   1024
#define NH   16
#define NDK  64
#define FDEC 1024
#define FD   16
#define KINR 784
#define KP   1024
#define MROWS (NB*NS)   // 8192

// ---------------- scratch (static __device__, no allocation) ----------------
__device__ float g_xcat[MROWS * KP];     // concat input, tf32-rounded
__device__ float g_x   [MROWS * FDEC];   // dense output (residual, fp32)
__device__ float g_xn  [MROWS * FDEC];   // LN output, tf32-rounded
__device__ float g_q   [MROWS * FDEC];
__device__ float g_k   [MROWS * FDEC];
__device__ float g_v   [MROWS * FDEC];
__device__ float g_o   [MROWS * FDEC];   // attention out, fp32
__device__ float g_wd  [FDEC * KP];      // rounded/padded weights
__device__ float g_wqr [FDEC * KP];
__device__ float g_wkr [FDEC * KP];
__device__ float g_wvr [FDEC * KP];
__device__ float g_wc  [FD * FDEC];      // dcw @ wo  [16][1024]
__device__ float g_cadd[FD];             // dcw . bo + dec_b

// ---------------- PTX helpers ------------------------------------------------
__device__ __forceinline__ uint32_t smem_u32(const void* p) {
    uint32_t a;
    asm("{ .reg .u64 t; cvta.to.shared.u64 t, %1; cvt.u32.u64 %0, t; }" : "=r"(a) : "l"(p));
    return a;
}

#define LDSM4(R, A) \
    asm volatile("ldmatrix.sync.aligned.m8n8.x4.shared.b16 {%0,%1,%2,%3}, [%4];" \
        : "=r"((R)[0]), "=r"((R)[1]), "=r"((R)[2]), "=r"((R)[3]) : "r"(A))

#define MMA_TF32(C, A, B0, B1) \
    asm volatile("mma.sync.aligned.m16n8k8.row.col.f32.tf32.tf32.f32 " \
        "{%0,%1,%2,%3},{%4,%5,%6,%7},{%8,%9},{%0,%1,%2,%3};" \
        : "+f"((C)[0]), "+f"((C)[1]), "+f"((C)[2]), "+f"((C)[3]) \
        : "r"((A)[0]), "r"((A)[1]), "r"((A)[2]), "r"((A)[3]), "r"(B0), "r"(B1))

__device__ __forceinline__ uint32_t to_tf32(float f) {
    uint32_t r;
    asm("cvt.rna.tf32.f32 %0, %1;" : "=r"(r) : "f"(f));
    return r;
}
__device__ __forceinline__ float tf32r(float f) {
    return __uint_as_float(to_tf32(f));
}

__device__ __forceinline__ void cpa16(uint32_t dst, const void* src) {
    asm volatile("cp.async.cg.shared.global [%0], [%1], 16;" :: "r"(dst), "l"(src));
}
#define CP_COMMIT() asm volatile("cp.async.commit_group;" ::: "memory")
#define CP_WAIT(n)  asm volatile("cp.async.wait_group %0;" :: "n"(n) : "memory")

// ---------------- producers (tf32-rounded outputs) ---------------------------
__global__ void __launch_bounds__(256) concat_k(
    const float* __restrict__ r, const float* __restrict__ z,
    float* __restrict__ xcat)
{
    int idx = blockIdx.x * 256 + threadIdx.x;
    if (idx >= MROWS * KP) return;
    int m = idx >> 10, f = idx & 1023;
    float v = (f < 16) ? r[m * 16 + f]
            : (f < KINR) ? z[(m >> 10) * 768 + (f - 16)] : 0.f;
    xcat[idx] = tf32r(v);
}

// weight round + pad: w [1024, Ksrc] -> tf32-rounded [1024, 1024]
__global__ void __launch_bounds__(256) roundpad_k(
    const float* __restrict__ w, int Ksrc, float* __restrict__ dst)
{
    int idx = blockIdx.x * 256 + threadIdx.x;
    if (idx >= FDEC * KP) return;
    int n = idx >> 10, k = idx & 1023;
    dst[idx] = (k < Ksrc) ? tf32r(w[n * Ksrc + k]) : 0.f;
}

// wc[n][c] = sum_j dcw[n][j] * wo[j][c]   (16 x 1024), exact fp32
// 64 blocks x 256 thr; thread owns one (n, c) output, c = blk*16 + (t&15).
__global__ void __launch_bounds__(256) wcomb_k(
    const float* __restrict__ dcw, const float* __restrict__ wo,
    float* __restrict__ wc)
{
    const int n = threadIdx.x >> 4;
    const int c = blockIdx.x * 16 + (threadIdx.x & 15);
    const float* dr = dcw + n * FDEC;
    float acc = 0.f;
    #pragma unroll 8
    for (int j = 0; j < FDEC; j++)
        acc += dr[j] * wo[(size_t)j * FDEC + c];
    wc[n * FDEC + c] = acc;
}

// cadd[n] = dec_b[n] + sum_k dcw[n][k] * bo[k]
__global__ void __launch_bounds__(512) cvec_k(
    const float* __restrict__ dcw, const float* __restrict__ bo,
    const float* __restrict__ dcb, float* __restrict__ cadd)
{
    const int n = threadIdx.x >> 5, lane = threadIdx.x & 31;
    float sum = 0.f;
    #pragma unroll
    for (int i = 0; i < 8; i++) {
        float4 a = ((const float4*)(dcw + n * FDEC))[lane + i * 32];
        float4 b = ((const float4*)bo)[lane + i * 32];
        sum += a.x * b.x + a.y * b.y + a.z * b.z + a.w * b.w;
    }
    #pragma unroll
    for (int o = 16; o; o >>= 1) sum += __shfl_xor_sync(0xffffffffu, sum, o);
    if (lane == 0) cadd[n] = sum + dcb[n];
}

// ---------------- LayerNorm (fp32 in, tf32-rounded out) ----------------------
__device__ __forceinline__ float blockReduce(float val, float* sh)
{
    __syncthreads();
    int lane = threadIdx.x & 31, wid = threadIdx.x >> 5;
    #pragma unroll
    for (int o = 16; o; o >>= 1) val += __shfl_xor_sync(0xffffffffu, val, o);
    if (lane == 0) sh[wid] = val;
    __syncthreads();
    if (wid == 0) {
        val = (lane < 8) ? sh[lane] : 0.f;
        #pragma unroll
        for (int o = 4; o; o >>= 1) val += __shfl_xor_sync(0xffffffffu, val, o);
        if (lane == 0) sh[0] = val;
    }
    __syncthreads();
    return sh[0];
}

__global__ void __launch_bounds__(256) ln_k(
    const float* __restrict__ x, const float* __restrict__ g,
    const float* __restrict__ beta, float* __restrict__ xn)
{
    __shared__ float red[32];
    int row = blockIdx.x;
    float4 v = ((const float4*)(x + (size_t)row * 1024))[threadIdx.x];
    float s = blockReduce(v.x + v.y + v.z + v.w, red);
    float mean = s * (1.0f / 1024.0f);
    float dx = v.x - mean, dy = v.y - mean, dz = v.z - mean, dw = v.w - mean;
    float s2 = blockReduce(dx*dx + dy*dy + dz*dz + dw*dw, red);
    float inv = rsqrtf(s2 * (1.0f / 1024.0f) + 1e-6f);
    float4 gg = ((const float4*)g)[threadIdx.x];
    float4 bb = ((const float4*)beta)[threadIdx.x];
    float4 o;
    o.x = tf32r(gg.x * dx * inv + bb.x);
    o.y = tf32r(gg.y * dy * inv + bb.y);
    o.z = tf32r(gg.z * dz * inv + bb.z);
    o.w = tf32r(gg.w * dw * inv + bb.w);
    ((float4*)(xn + (size_t)row * 1024))[threadIdx.x] = o;
}

// ---------------- tf32 mma GEMM with ldmatrix fragments ----------------------
// C[M,1024] = A[M,1024] @ W[1024,1024]^T + bias. Operands pre-rounded to tf32.
// Block 128x128, 256 thr (8 warps, 4m x 2n), warp tile 32x64, K-tile 32,
// 3-stage cp.async. MODE 0: plain store, MODE 1: qkv scatter [B,H,S,DK].
#define GSTR  36
#define TILE_BYTES (128 * GSTR * 4)
#define STAGE_B (2 * TILE_BYTES)
#define GEMM_SMEM (3 * STAGE_B)

template<int MODE>
__global__ void __launch_bounds__(256) gemm_tf32(
    const float* __restrict__ A, const float* __restrict__ Bw,
    const float* __restrict__ bias, float* __restrict__ C)
{
    extern __shared__ char sm[];
    const uint32_t sbase = smem_u32(sm);
    const int tid = threadIdx.x, lane = tid & 31, wid = tid >> 5;
    const int g4 = lane >> 2, t4 = lane & 3;
    const int bm = blockIdx.y * 128, bn = blockIdx.x * 128;
    const int wm = (wid & 3) * 32, wn = (wid >> 2) * 64;

    float acc[2][8][4];
    #pragma unroll
    for (int a = 0; a < 2; a++)
        #pragma unroll
        for (int b = 0; b < 8; b++)
            #pragma unroll
            for (int c = 0; c < 4; c++) acc[a][b][c] = 0.f;

    const uint32_t aoff =
        ((uint32_t)(wm + (lane & 7) + ((lane >> 3) & 1) * 8) * GSTR
         + ((lane >> 4) << 2)) * 4;
    const uint32_t boff =
        ((uint32_t)(wn + (lane & 7)) * GSTR + ((lane >> 3) & 3) * 4) * 4;

    auto load_stage = [&](int slot, int k0) {
        const uint32_t sa = sbase + slot * STAGE_B;
        #pragma unroll
        for (int c = 0; c < 4; c++) {
            int chunk = tid + c * 256;
            int row = chunk >> 3, seg = chunk & 7;
            cpa16(sa + row * (GSTR*4) + seg * 16,
                  A + (size_t)(bm + row) * KP + k0 + seg * 4);
        }
        const uint32_t sb = sa + TILE_BYTES;
        #pragma unroll
        for (int c = 0; c < 4; c++) {
            int chunk = tid + c * 256;
            int row = chunk >> 3, seg = chunk & 7;
            cpa16(sb + row * (GSTR*4) + seg * 16,
                  Bw + (size_t)(bn + row) * KP + k0 + seg * 4);
        }
    };

    load_stage(0, 0);  CP_COMMIT();
    load_stage(1, 32); CP_COMMIT();

    for (int i = 0; i < 32; i++) {
        if (i < 31) { CP_WAIT(1); } else { CP_WAIT(0); }
        __syncthreads();
        if (i + 2 < 32) { load_stage((i + 2) % 3, (i + 2) * 32); CP_COMMIT(); }

        const uint32_t As = sbase + (i % 3) * STAGE_B;
        const uint32_t Bs = As + TILE_BYTES;

        uint32_t a[4][2][4];
        #pragma unroll
        for (int kk = 0; kk < 4; kk++)
            #pragma unroll
            for (int am = 0; am < 2; am++)
                LDSM4(a[kk][am], As + aoff + am * (16 * GSTR * 4) + kk * 32);

        #pragma unroll
        for (int nt = 0; nt < 8; nt++) {
            uint32_t b01[4], b23[4];
            const uint32_t bb = Bs + boff + nt * (8 * GSTR * 4);
            LDSM4(b01, bb);
            LDSM4(b23, bb + 64);
            MMA_TF32(acc[0][nt], a[0][0], b01[0], b01[1]);
            MMA_TF32(acc[1][nt], a[0][1], b01[0], b01[1]);
            MMA_TF32(acc[0][nt], a[1][0], b01[2], b01[3]);
            MMA_TF32(acc[1][nt], a[1][1], b01[2], b01[3]);
            MMA_TF32(acc[0][nt], a[2][0], b23[0], b23[1]);
            MMA_TF32(acc[1][nt], a[2][1], b23[0], b23[1]);
            MMA_TF32(acc[0][nt], a[3][0], b23[2], b23[3]);
            MMA_TF32(acc[1][nt], a[3][1], b23[2], b23[3]);
        }
    }

    #pragma unroll
    for (int am = 0; am < 2; am++) {
        #pragma unroll
        for (int nt = 0; nt < 8; nt++) {
            int mrow = bm + wm + am * 16 + g4;
            int ncol = bn + wn + nt * 8 + t4 * 2;
            float b0 = bias[ncol], b1 = bias[ncol + 1];
            #pragma unroll
            for (int r = 0; r < 2; r++) {
                int m = mrow + r * 8;
                float v0 = acc[am][nt][r * 2]     + b0;
                float v1 = acc[am][nt][r * 2 + 1] + b1;
                if (MODE == 0) {
                    *(float2*)&C[(size_t)m * 1024 + ncol] = make_float2(v0, v1);
                } else {
                    int bb = m >> 10, s = m & 1023, h = ncol >> 6, d = ncol & 63;
                    *(float2*)&C[(size_t)(((bb << 4) + h) * 1024 + s) * 64 + d] =
                        make_float2(v0, v1);
                }
            }
        }
    }
}

// ---------------- fused decode: out = x.dw + o.wc + cadd, transposed ---------
__global__ void __launch_bounds__(512) dec2_k(
    const float* __restrict__ x, const float* __restrict__ o,
    const float* __restrict__ dw, const float* __restrict__ wc,
    const float* __restrict__ cadd, float* __restrict__ out)
{
    const int m = blockIdx.x;
    const int b = m >> 10, s = m & 1023;
    const int n = threadIdx.x >> 5;
    const int lane = threadIdx.x & 31;
    const float4* xr = (const float4*)(x  + (size_t)m * FDEC);
    const float4* orr = (const float4*)(o + (size_t)m * FDEC);
    const float4* wr = (const float4*)(dw + (size_t)n * FDEC);
    const float4* cr = (const float4*)(wc + (size_t)n * FDEC);
    float sum = 0.f;
    #pragma unroll
    for (int i = 0; i < 8; i++) {
        float4 a = xr[lane + i * 32];
        float4 w = wr[lane + i * 32];
        float4 oo = orr[lane + i * 32];
        float4 c = cr[lane + i * 32];
        sum += a.x * w.x + a.y * w.y + a.z * w.z + a.w * w.w;
        sum += oo.x * c.x + oo.y * c.y + oo.z * c.z + oo.w * c.w;
    }
    #pragma unroll
    for (int oo = 16; oo; oo >>= 1) sum += __shfl_xor_sync(0xffffffffu, sum, oo);
    if (lane == 0)
        out[(size_t)(b * FD + n) * NS + s] = sum + cadd[n];
}

// ---------------- tf32 mma flash attention with ALiBi ------------------------
#define ASTR 68
#define ATTN_SMEM (3 * 64 * ASTR * (int)sizeof(float))

__global__ void __launch_bounds__(128) attn_tc(
    const float* __restrict__ q, const float* __restrict__ k,
    const float* __restrict__ v, float* __restrict__ o)
{
    extern __shared__ float smf[];
    float* Ks = smf;
    float* Vs = Ks + 64 * ASTR;
    float* Ps = Vs + 64 * ASTR;

    const int qc = blockIdx.x, h = blockIdx.y, b = blockIdx.z;
    const int tid = threadIdx.x, lane = tid & 31, w = tid >> 5;
    const int g4 = lane >> 2, t4 = lane & 3;

    const size_t head = (size_t)(b * NH + h) * NS * NDK;
    const float* qb = q + head;
    const float* kb = k + head;
    const float* vb = v + head;

    uint32_t qa[8][4];
    {
        const int r0 = qc * 64 + w * 16 + g4;
        #pragma unroll
        for (int kk = 0; kk < 8; kk++) {
            int c0 = kk * 8 + t4;
            qa[kk][0] = to_tf32(qb[(size_t)r0 * 64 + c0] * 0.125f);
            qa[kk][1] = to_tf32(qb[(size_t)(r0 + 8) * 64 + c0] * 0.125f);
            qa[kk][2] = to_tf32(qb[(size_t)r0 * 64 + c0 + 4] * 0.125f);
            qa[kk][3] = to_tf32(qb[(size_t)(r0 + 8) * 64 + c0 + 4] * 0.125f);
        }
    }

    const float slope = exp2f(-0.5f * (float)(h + 1));
    float oacc[8][4];
    #pragma unroll
    for (int dt = 0; dt < 8; dt++)
        #pragma unroll
        for (int c = 0; c < 4; c++) oacc[dt][c] = 0.f;
    float mrow[2] = { -1e30f, -1e30f };
    float lrow[2] = { 0.f, 0.f };

    const int lrow_ld = tid >> 1, lcol0 = (tid & 1) * 32;

    for (int kc = 0; kc <= qc; kc++) {
        {
            const float* ksrc = kb + (size_t)(kc * 64 + lrow_ld) * 64 + lcol0;
            const float* vsrc = vb + (size_t)(kc * 64 + lrow_ld) * 64 + lcol0;
            float* kd = Ks + lrow_ld * ASTR + lcol0;
            #pragma unroll
            for (int c = 0; c < 32; c += 4) {
                float4 t = *(const float4*)(ksrc + c);
                *(float4*)(kd + c) = t;
                float4 tv = *(const float4*)(vsrc + c);
                Vs[(lcol0 + c + 0) * ASTR + lrow_ld] = tv.x;
                Vs[(lcol0 + c + 1) * ASTR + lrow_ld] = tv.y;
                Vs[(lcol0 + c + 2) * ASTR + lrow_ld] = tv.z;
                Vs[(lcol0 + c + 3) * ASTR + lrow_ld] = tv.w;
            }
        }
        __syncthreads();

        float sc[8][4];
        #pragma unroll
        for (int nt = 0; nt < 8; nt++) {
            sc[nt][0] = sc[nt][1] = sc[nt][2] = sc[nt][3] = 0.f;
            #pragma unroll
            for (int kk = 0; kk < 8; kk++) {
                const float* kp = &Ks[(nt * 8 + g4) * ASTR + kk * 8 + t4];
                uint32_t b0 = to_tf32(kp[0]);
                uint32_t b1 = to_tf32(kp[4]);
                MMA_TF32(sc[nt], qa[kk], b0, b1);
            }
        }

        const bool diag = (kc == qc);
        #pragma unroll
        for (int half = 0; half < 2; half++) {
            const int wr = w * 16 + g4 + half * 8;
            const int ig = qc * 64 + wr;
            float mx = -1e30f;
            #pragma unroll
            for (int nt = 0; nt < 8; nt++) {
                #pragma unroll
                for (int e = 0; e < 2; e++) {
                    int jl = nt * 8 + t4 * 2 + e;
                    int jg = kc * 64 + jl;
                    float val = sc[nt][half * 2 + e] + slope * (float)jg;
                    if (diag && jg > ig) val -= 1e9f;
                    sc[nt][half * 2 + e] = val;
                    mx = fmaxf(mx, val);
                }
            }
            mx = fmaxf(mx, __shfl_xor_sync(0xffffffffu, mx, 1));
            mx = fmaxf(mx, __shfl_xor_sync(0xffffffffu, mx, 2));
            float mnew = fmaxf(mrow[half], mx);
            float corr = __expf(mrow[half] - mnew);
            mrow[half] = mnew;
            float rs = 0.f;
            #pragma unroll
            for (int nt = 0; nt < 8; nt++) {
                #pragma unroll
                for (int e = 0; e < 2; e++) {
                    float p = __expf(sc[nt][half * 2 + e] - mnew);
                    rs += p;
                    Ps[wr * ASTR + nt * 8 + t4 * 2 + e] = p;
                }
            }
            rs += __shfl_xor_sync(0xffffffffu, rs, 1);
            rs += __shfl_xor_sync(0xffffffffu, rs, 2);
            lrow[half] = lrow[half] * corr + rs;
            #pragma unroll
            for (int dt = 0; dt < 8; dt++) {
                oacc[dt][half * 2]     *= corr;
                oacc[dt][half * 2 + 1] *= corr;
            }
        }
        __syncwarp();

        #pragma unroll
        for (int kk = 0; kk < 8; kk++) {
            uint32_t pa[4];
            const int pr = w * 16 + g4;
            pa[0] = to_tf32(Ps[pr * ASTR + kk * 8 + t4]);
            pa[1] = to_tf32(Ps[(pr + 8) * ASTR + kk * 8 + t4]);
            pa[2] = to_tf32(Ps[pr * ASTR + kk * 8 + t4 + 4]);
            pa[3] = to_tf32(Ps[(pr + 8) * ASTR + kk * 8 + t4 + 4]);
            #pragma unroll
            for (int dt = 0; dt < 8; dt++) {
                const float* vp = &Vs[(dt * 8 + g4) * ASTR + kk * 8 + t4];
                uint32_t b0 = to_tf32(vp[0]);
                uint32_t b1 = to_tf32(vp[4]);
                MMA_TF32(oacc[dt], pa, b0, b1);
            }
        }
        __syncthreads();
    }

    #pragma unroll
    for (int half = 0; half < 2; half++) {
        const int sg = qc * 64 + w * 16 + g4 + half * 8;
        const float inv = 1.0f / lrow[half];
        const size_t base = (size_t)(b * NS + sg) * (NH * NDK) + h * NDK;
        #pragma unroll
        for (int dt = 0; dt < 8; dt++) {
            int d = dt * 8 + t4 * 2;
            float v0 = oacc[dt][half * 2]     * inv;
            float v1 = oacc[dt][half * 2 + 1] * inv;
            *(float2*)&o[base + d] = make_float2(v0, v1);
        }
    }
}

// ---------------- launcher ----------------------------------------------------
extern "C" void kernel_launch(void* const* d_in, const int* in_sizes, int n_in,
                              void* d_out, int out_size)
{
    const float* z   = (const float*)d_in[0];
    const float* r   = (const float*)d_in[1];
    const float* dwn = (const float*)d_in[2];
    const float* dbn = (const float*)d_in[3];
    const float* lng = (const float*)d_in[4];
    const float* lnb = (const float*)d_in[5];
    const float* wq  = (const float*)d_in[6];
    const float* bq  = (const float*)d_in[7];
    const float* wk  = (const float*)d_in[8];
    const float* bk  = (const float*)d_in[9];
    const float* wv  = (const float*)d_in[10];
    const float* bv  = (const float*)d_in[11];
    const float* wo  = (const float*)d_in[12];
    const float* bo  = (const float*)d_in[13];
    const float* dcw = (const float*)d_in[14];
    const float* dcb = (const float*)d_in[15];
    float* out = (float*)d_out;

    float *xcat, *x, *xn, *q, *k, *v, *o;
    float *wd, *wqr, *wkr, *wvr, *wc, *cadd;
    cudaGetSymbolAddress((void**)&xcat, g_xcat);
    cudaGetSymbolAddress((void**)&x,    g_x);
    cudaGetSymbolAddress((void**)&xn,   g_xn);
    cudaGetSymbolAddress((void**)&q,    g_q);
    cudaGetSymbolAddress((void**)&k,    g_k);
    cudaGetSymbolAddress((void**)&v,    g_v);
    cudaGetSymbolAddress((void**)&o,    g_o);
    cudaGetSymbolAddress((void**)&wd,   g_wd);
    cudaGetSymbolAddress((void**)&wqr,  g_wqr);
    cudaGetSymbolAddress((void**)&wkr,  g_wkr);
    cudaGetSymbolAddress((void**)&wvr,  g_wvr);
    cudaGetSymbolAddress((void**)&wc,   g_wc);
    cudaGetSymbolAddress((void**)&cadd, g_cadd);

    cudaFuncSetAttribute(gemm_tf32<0>, cudaFuncAttributeMaxDynamicSharedMemorySize, GEMM_SMEM);
    cudaFuncSetAttribute(gemm_tf32<1>, cudaFuncAttributeMaxDynamicSharedMemorySize, GEMM_SMEM);
    cudaFuncSetAttribute(attn_tc,      cudaFuncAttributeMaxDynamicSharedMemorySize, ATTN_SMEM);

    const int WELTS = FDEC * KP;
    concat_k<<<(MROWS * KP + 255) / 256, 256>>>(r, z, xcat);
    roundpad_k<<<(WELTS + 255) / 256, 256>>>(dwn, KINR, wd);
    roundpad_k<<<(WELTS + 255) / 256, 256>>>(wq, FDEC, wqr);
    roundpad_k<<<(WELTS + 255) / 256, 256>>>(wk, FDEC, wkr);
    roundpad_k<<<(WELTS + 255) / 256, 256>>>(wv, FDEC, wvr);
    wcomb_k<<<64, 256>>>(dcw, wo, wc);
    cvec_k<<<1, 512>>>(dcw, bo, dcb, cadd);

    dim3 ggrid(8, 64);
    gemm_tf32<0><<<ggrid, 256, GEMM_SMEM>>>(xcat, wd, dbn, x);
    ln_k<<<MROWS, 256>>>(x, lng, lnb, xn);
    gemm_tf32<1><<<ggrid, 256, GEMM_SMEM>>>(xn, wqr, bq, q);
    gemm_tf32<1><<<ggrid, 256, GEMM_SMEM>>>(xn, wkr, bk, k);
    gemm_tf32<1><<<ggrid, 256, GEMM_SMEM>>>(xn, wvr, bv, v);
    attn_tc<<<dim3(NS / 64, NH, NB), 128, ATTN_SMEM>>>(q, k, v, o);
    dec2_k<<<MROWS, 512>>>(x, o, dcw, wc, cadd, out);
}

// round 13
// speedup vs baseline: 1.0825x; 1.0412x over previous
#include <cuda_runtime.h>
#include <cuda_bf16.h>
#include <cstdint>
#include <math.h>

// Problem dims (fixed)
#define NB   8
#define NS   1024
#define NH   16
#define NDK  64
#define FDEC 1024
#define FD   16
#define KINR 784
#define KP   1024
#define MROWS (NB*NS)   // 8192

// ---------------- scratch (static __device__, no allocation) ----------------
__device__ float g_xcat[MROWS * KP];     // concat input, tf32-rounded
__device__ float g_x   [MROWS * FDEC];   // dense output (residual, fp32)
__device__ float g_xn  [MROWS * FDEC];   // LN output, tf32-rounded
__device__ float g_q   [MROWS * FDEC];   // tf32-rounded
__device__ float g_k   [MROWS * FDEC];   // tf32-rounded
__device__ float g_v   [MROWS * FDEC];   // tf32-rounded
__device__ float g_o   [MROWS * FDEC];   // attention out, fp32
__device__ float g_wd  [FDEC * KP];
__device__ float g_wqr [FDEC * KP];
__device__ float g_wkr [FDEC * KP];
__device__ float g_wvr [FDEC * KP];
__device__ float g_wc  [FD * FDEC];      // dcw @ wo
__device__ float g_cadd[FD];             // dcw . bo + dec_b

// ---------------- PTX helpers ------------------------------------------------
__device__ __forceinline__ uint32_t smem_u32(const void* p) {
    uint32_t a;
    asm("{ .reg .u64 t; cvta.to.shared.u64 t, %1; cvt.u32.u64 %0, t; }" : "=r"(a) : "l"(p));
    return a;
}

#define LDSM4(R, A) \
    asm volatile("ldmatrix.sync.aligned.m8n8.x4.shared.b16 {%0,%1,%2,%3}, [%4];" \
        : "=r"((R)[0]), "=r"((R)[1]), "=r"((R)[2]), "=r"((R)[3]) : "r"(A))

#define MMA_TF32(C, A, B0, B1) \
    asm volatile("mma.sync.aligned.m16n8k8.row.col.f32.tf32.tf32.f32 " \
        "{%0,%1,%2,%3},{%4,%5,%6,%7},{%8,%9},{%0,%1,%2,%3};" \
        : "+f"((C)[0]), "+f"((C)[1]), "+f"((C)[2]), "+f"((C)[3]) \
        : "r"((A)[0]), "r"((A)[1]), "r"((A)[2]), "r"((A)[3]), "r"(B0), "r"(B1))

__device__ __forceinline__ uint32_t to_tf32(float f) {
    uint32_t r;
    asm("cvt.rna.tf32.f32 %0, %1;" : "=r"(r) : "f"(f));
    return r;
}
__device__ __forceinline__ float tf32r(float f) {
    return __uint_as_float(to_tf32(f));
}

__device__ __forceinline__ void cpa16(uint32_t dst, const void* src) {
    asm volatile("cp.async.cg.shared.global [%0], [%1], 16;" :: "r"(dst), "l"(src));
}
#define CP_COMMIT() asm volatile("cp.async.commit_group;" ::: "memory")
#define CP_WAIT(n)  asm volatile("cp.async.wait_group %0;" :: "n"(n) : "memory")

// ---------------- producers (tf32-rounded outputs) ---------------------------
__global__ void __launch_bounds__(256) concat_k(
    const float* __restrict__ r, const float* __restrict__ z,
    float* __restrict__ xcat)
{
    int idx = blockIdx.x * 256 + threadIdx.x;
    if (idx >= MROWS * KP) return;
    int m = idx >> 10, f = idx & 1023;
    float v = (f < 16) ? r[m * 16 + f]
            : (f < KINR) ? z[(m >> 10) * 768 + (f - 16)] : 0.f;
    xcat[idx] = tf32r(v);
}

__global__ void __launch_bounds__(256) roundpad_k(
    const float* __restrict__ w, int Ksrc, float* __restrict__ dst)
{
    int idx = blockIdx.x * 256 + threadIdx.x;
    if (idx >= FDEC * KP) return;
    int n = idx >> 10, k = idx & 1023;
    dst[idx] = (k < Ksrc) ? tf32r(w[n * Ksrc + k]) : 0.f;
}

// wc[n][c] = sum_j dcw[n][j] * wo[j][c]   (16 x 1024), exact fp32
__global__ void __launch_bounds__(256) wcomb_k(
    const float* __restrict__ dcw, const float* __restrict__ wo,
    float* __restrict__ wc)
{
    const int n = threadIdx.x >> 4;
    const int c = blockIdx.x * 16 + (threadIdx.x & 15);
    const float* dr = dcw + n * FDEC;
    float acc = 0.f;
    #pragma unroll 8
    for (int j = 0; j < FDEC; j++)
        acc += dr[j] * wo[(size_t)j * FDEC + c];
    wc[n * FDEC + c] = acc;
}

__global__ void __launch_bounds__(512) cvec_k(
    const float* __restrict__ dcw, const float* __restrict__ bo,
    const float* __restrict__ dcb, float* __restrict__ cadd)
{
    const int n = threadIdx.x >> 5, lane = threadIdx.x & 31;
    float sum = 0.f;
    #pragma unroll
    for (int i = 0; i < 8; i++) {
        float4 a = ((const float4*)(dcw + n * FDEC))[lane + i * 32];
        float4 b = ((const float4*)bo)[lane + i * 32];
        sum += a.x * b.x + a.y * b.y + a.z * b.z + a.w * b.w;
    }
    #pragma unroll
    for (int o = 16; o; o >>= 1) sum += __shfl_xor_sync(0xffffffffu, sum, o);
    if (lane == 0) cadd[n] = sum + dcb[n];
}

// ---------------- LayerNorm (fp32 in, tf32-rounded out) ----------------------
__device__ __forceinline__ float blockReduce(float val, float* sh)
{
    __syncthreads();
    int lane = threadIdx.x & 31, wid = threadIdx.x >> 5;
    #pragma unroll
    for (int o = 16; o; o >>= 1) val += __shfl_xor_sync(0xffffffffu, val, o);
    if (lane == 0) sh[wid] = val;
    __syncthreads();
    if (wid == 0) {
        val = (lane < 8) ? sh[lane] : 0.f;
        #pragma unroll
        for (int o = 4; o; o >>= 1) val += __shfl_xor_sync(0xffffffffu, val, o);
        if (lane == 0) sh[0] = val;
    }
    __syncthreads();
    return sh[0];
}

__global__ void __launch_bounds__(256) ln_k(
    const float* __restrict__ x, const float* __restrict__ g,
    const float* __restrict__ beta, float* __restrict__ xn)
{
    __shared__ float red[32];
    int row = blockIdx.x;
    float4 v = ((const float4*)(x + (size_t)row * 1024))[threadIdx.x];
    float s = blockReduce(v.x + v.y + v.z + v.w, red);
    float mean = s * (1.0f / 1024.0f);
    float dx = v.x - mean, dy = v.y - mean, dz = v.z - mean, dw = v.w - mean;
    float s2 = blockReduce(dx*dx + dy*dy + dz*dz + dw*dw, red);
    float inv = rsqrtf(s2 * (1.0f / 1024.0f) + 1e-6f);
    float4 gg = ((const float4*)g)[threadIdx.x];
    float4 bb = ((const float4*)beta)[threadIdx.x];
    float4 o;
    o.x = tf32r(gg.x * dx * inv + bb.x);
    o.y = tf32r(gg.y * dy * inv + bb.y);
    o.z = tf32r(gg.z * dz * inv + bb.z);
    o.w = tf32r(gg.w * dw * inv + bb.w);
    ((float4*)(xn + (size_t)row * 1024))[threadIdx.x] = o;
}

// ---------------- tf32 mma GEMM with ldmatrix fragments ----------------------
// MODE 0: plain fp32 store; MODE 1: qkv scatter [B,H,S,DK], tf32-rounded.
#define GSTR  36
#define TILE_BYTES (128 * GSTR * 4)
#define STAGE_B (2 * TILE_BYTES)
#define GEMM_SMEM (3 * STAGE_B)

template<int MODE>
__global__ void __launch_bounds__(256) gemm_tf32(
    const float* __restrict__ A, const float* __restrict__ Bw,
    const float* __restrict__ bias, float* __restrict__ C)
{
    extern __shared__ char sm[];
    const uint32_t sbase = smem_u32(sm);
    const int tid = threadIdx.x, lane = tid & 31, wid = tid >> 5;
    const int g4 = lane >> 2, t4 = lane & 3;
    const int bm = blockIdx.y * 128, bn = blockIdx.x * 128;
    const int wm = (wid & 3) * 32, wn = (wid >> 2) * 64;

    float acc[2][8][4];
    #pragma unroll
    for (int a = 0; a < 2; a++)
        #pragma unroll
        for (int b = 0; b < 8; b++)
            #pragma unroll
            for (int c = 0; c < 4; c++) acc[a][b][c] = 0.f;

    const uint32_t aoff =
        ((uint32_t)(wm + (lane & 7) + ((lane >> 3) & 1) * 8) * GSTR
         + ((lane >> 4) << 2)) * 4;
    const uint32_t boff =
        ((uint32_t)(wn + (lane & 7)) * GSTR + ((lane >> 3) & 3) * 4) * 4;

    auto load_stage = [&](int slot, int k0) {
        const uint32_t sa = sbase + slot * STAGE_B;
        #pragma unroll
        for (int c = 0; c < 4; c++) {
            int chunk = tid + c * 256;
            int row = chunk >> 3, seg = chunk & 7;
            cpa16(sa + row * (GSTR*4) + seg * 16,
                  A + (size_t)(bm + row) * KP + k0 + seg * 4);
        }
        const uint32_t sb = sa + TILE_BYTES;
        #pragma unroll
        for (int c = 0; c < 4; c++) {
            int chunk = tid + c * 256;
            int row = chunk >> 3, seg = chunk & 7;
            cpa16(sb + row * (GSTR*4) + seg * 16,
                  Bw + (size_t)(bn + row) * KP + k0 + seg * 4);
        }
    };

    load_stage(0, 0);  CP_COMMIT();
    load_stage(1, 32); CP_COMMIT();

    for (int i = 0; i < 32; i++) {
        if (i < 31) { CP_WAIT(1); } else { CP_WAIT(0); }
        __syncthreads();
        if (i + 2 < 32) { load_stage((i + 2) % 3, (i + 2) * 32); CP_COMMIT(); }

        const uint32_t As = sbase + (i % 3) * STAGE_B;
        const uint32_t Bs = As + TILE_BYTES;

        uint32_t a[4][2][4];
        #pragma unroll
        for (int kk = 0; kk < 4; kk++)
            #pragma unroll
            for (int am = 0; am < 2; am++)
                LDSM4(a[kk][am], As + aoff + am * (16 * GSTR * 4) + kk * 32);

        #pragma unroll
        for (int nt = 0; nt < 8; nt++) {
            uint32_t b01[4], b23[4];
            const uint32_t bb = Bs + boff + nt * (8 * GSTR * 4);
            LDSM4(b01, bb);
            LDSM4(b23, bb + 64);
            MMA_TF32(acc[0][nt], a[0][0], b01[0], b01[1]);
            MMA_TF32(acc[1][nt], a[0][1], b01[0], b01[1]);
            MMA_TF32(acc[0][nt], a[1][0], b01[2], b01[3]);
            MMA_TF32(acc[1][nt], a[1][1], b01[2], b01[3]);
            MMA_TF32(acc[0][nt], a[2][0], b23[0], b23[1]);
            MMA_TF32(acc[1][nt], a[2][1], b23[0], b23[1]);
            MMA_TF32(acc[0][nt], a[3][0], b23[2], b23[3]);
            MMA_TF32(acc[1][nt], a[3][1], b23[2], b23[3]);
        }
    }

    #pragma unroll
    for (int am = 0; am < 2; am++) {
        #pragma unroll
        for (int nt = 0; nt < 8; nt++) {
            int mrow = bm + wm + am * 16 + g4;
            int ncol = bn + wn + nt * 8 + t4 * 2;
            float b0 = bias[ncol], b1 = bias[ncol + 1];
            #pragma unroll
            for (int r = 0; r < 2; r++) {
                int m = mrow + r * 8;
                float v0 = acc[am][nt][r * 2]     + b0;
                float v1 = acc[am][nt][r * 2 + 1] + b1;
                if (MODE == 0) {
                    *(float2*)&C[(size_t)m * 1024 + ncol] = make_float2(v0, v1);
                } else {
                    int bb = m >> 10, s = m & 1023, h = ncol >> 6, d = ncol & 63;
                    *(float2*)&C[(size_t)(((bb << 4) + h) * 1024 + s) * 64 + d] =
                        make_float2(tf32r(v0), tf32r(v1));
                }
            }
        }
    }
}

// ---------------- fused decode: out = x.dw + o.wc + cadd, transposed ---------
__global__ void __launch_bounds__(512) dec2_k(
    const float* __restrict__ x, const float* __restrict__ o,
    const float* __restrict__ dw, const float* __restrict__ wc,
    const float* __restrict__ cadd, float* __restrict__ out)
{
    const int m = blockIdx.x;
    const int b = m >> 10, s = m & 1023;
    const int n = threadIdx.x >> 5;
    const int lane = threadIdx.x & 31;
    const float4* xr = (const float4*)(x  + (size_t)m * FDEC);
    const float4* orr = (const float4*)(o + (size_t)m * FDEC);
    const float4* wr = (const float4*)(dw + (size_t)n * FDEC);
    const float4* cr = (const float4*)(wc + (size_t)n * FDEC);
    float sum = 0.f;
    #pragma unroll
    for (int i = 0; i < 8; i++) {
        float4 a = xr[lane + i * 32];
        float4 w = wr[lane + i * 32];
        float4 oo = orr[lane + i * 32];
        float4 c = cr[lane + i * 32];
        sum += a.x * w.x + a.y * w.y + a.z * w.z + a.w * w.w;
        sum += oo.x * c.x + oo.y * c.y + oo.z * c.z + oo.w * c.w;
    }
    #pragma unroll
    for (int oo = 16; oo; oo >>= 1) sum += __shfl_xor_sync(0xffffffffu, sum, oo);
    if (lane == 0)
        out[(size_t)(b * FD + n) * NS + s] = sum + cadd[n];
}

// ---------------- tf32 mma flash attention, ldmatrix fragments ---------------
// q/k/v pre-rounded to tf32 in memory. All fragment loads via ldmatrix.x4 on
// f32-viewed-as-b16 tiles (same mappings as the verified GEMM).
#define ASTR 68
#define ATTN_SMEM (3 * 64 * ASTR * (int)sizeof(float))

__global__ void __launch_bounds__(128) attn_tc(
    const float* __restrict__ q, const float* __restrict__ k,
    const float* __restrict__ v, float* __restrict__ o)
{
    extern __shared__ float smf[];
    float* Ks = smf;                 // [64][68]  K[j][d]
    float* Vs = Ks + 64 * ASTR;      // [64][68]  V^T: Vs[d][j]
    float* Ps = Vs + 64 * ASTR;      // [64][68]  P[row][j], tf32-rounded

    const int qc = blockIdx.x, h = blockIdx.y, b = blockIdx.z;
    const int tid = threadIdx.x, lane = tid & 31, w = tid >> 5;
    const int g4 = lane >> 2, t4 = lane & 3;

    const uint32_t sKs = smem_u32(Ks), sVs = smem_u32(Vs), sPs = smem_u32(Ps);

    const size_t head = (size_t)(b * NH + h) * NS * NDK;
    const float* qb = q + head;
    const float* kb = k + head;
    const float* vb = v + head;

    // Q a-fragments: values pre-rounded; *0.125f is exact -> still tf32.
    uint32_t qa[8][4];
    {
        const int r0 = qc * 64 + w * 16 + g4;
        #pragma unroll
        for (int kk = 0; kk < 8; kk++) {
            int c0 = kk * 8 + t4;
            qa[kk][0] = __float_as_uint(qb[(size_t)r0 * 64 + c0] * 0.125f);
            qa[kk][1] = __float_as_uint(qb[(size_t)(r0 + 8) * 64 + c0] * 0.125f);
            qa[kk][2] = __float_as_uint(qb[(size_t)r0 * 64 + c0 + 4] * 0.125f);
            qa[kk][3] = __float_as_uint(qb[(size_t)(r0 + 8) * 64 + c0 + 4] * 0.125f);
        }
    }

    // ldmatrix per-thread offsets (byte):
    // B-frag pattern (K rows j / V rows d): rows lane&7, col-seg (lane>>3)&3.
    const uint32_t bfrag = ((uint32_t)(lane & 7) * ASTR + ((lane >> 3) & 3) * 4) * 4;
    // A-frag pattern for P: rows w*16 + (lane&7) + ((lane>>3)&1)*8, seg (lane>>4)*4.
    const uint32_t pfrag =
        ((uint32_t)(w * 16 + (lane & 7) + ((lane >> 3) & 1) * 8) * ASTR
         + ((lane >> 4) << 2)) * 4;

    const float slope = exp2f(-0.5f * (float)(h + 1));
    float oacc[8][4];
    #pragma unroll
    for (int dt = 0; dt < 8; dt++)
        #pragma unroll
        for (int c = 0; c < 4; c++) oacc[dt][c] = 0.f;
    float mrow[2] = { -1e30f, -1e30f };
    float lrow[2] = { 0.f, 0.f };

    const int lrow_ld = tid >> 1, lcol0 = (tid & 1) * 32;

    for (int kc = 0; kc <= qc; kc++) {
        // load K [j][d]; V transposed [d][j]
        {
            const float* ksrc = kb + (size_t)(kc * 64 + lrow_ld) * 64 + lcol0;
            const float* vsrc = vb + (size_t)(kc * 64 + lrow_ld) * 64 + lcol0;
            float* kd = Ks + lrow_ld * ASTR + lcol0;
            #pragma unroll
            for (int c = 0; c < 32; c += 4) {
                float4 t = *(const float4*)(ksrc + c);
                *(float4*)(kd + c) = t;
                float4 tv = *(const float4*)(vsrc + c);
                Vs[(lcol0 + c + 0) * ASTR + lrow_ld] = tv.x;
                Vs[(lcol0 + c + 1) * ASTR + lrow_ld] = tv.y;
                Vs[(lcol0 + c + 2) * ASTR + lrow_ld] = tv.z;
                Vs[(lcol0 + c + 3) * ASTR + lrow_ld] = tv.w;
            }
        }
        __syncthreads();

        // S = Q K^T : per nt, 4 LDSM4 cover d 0..63 (kk pairs), 8 mma
        float sc[8][4];
        #pragma unroll
        for (int nt = 0; nt < 8; nt++) {
            sc[nt][0] = sc[nt][1] = sc[nt][2] = sc[nt][3] = 0.f;
            const uint32_t kb_ = sKs + bfrag + nt * (8 * ASTR * 4);
            uint32_t b0[4], b1[4], b2[4], b3[4];
            LDSM4(b0, kb_);
            LDSM4(b1, kb_ + 64);
            LDSM4(b2, kb_ + 128);
            LDSM4(b3, kb_ + 192);
            MMA_TF32(sc[nt], qa[0], b0[0], b0[1]);
            MMA_TF32(sc[nt], qa[1], b0[2], b0[3]);
            MMA_TF32(sc[nt], qa[2], b1[0], b1[1]);
            MMA_TF32(sc[nt], qa[3], b1[2], b1[3]);
            MMA_TF32(sc[nt], qa[4], b2[0], b2[1]);
            MMA_TF32(sc[nt], qa[5], b2[2], b2[3]);
            MMA_TF32(sc[nt], qa[6], b3[0], b3[1]);
            MMA_TF32(sc[nt], qa[7], b3[2], b3[3]);
        }

        // softmax; Ps written tf32-rounded
        const bool diag = (kc == qc);
        #pragma unroll
        for (int half = 0; half < 2; half++) {
            const int wr = w * 16 + g4 + half * 8;
            const int ig = qc * 64 + wr;
            float mx = -1e30f;
            #pragma unroll
            for (int nt = 0; nt < 8; nt++) {
                #pragma unroll
                for (int e = 0; e < 2; e++) {
                    int jl = nt * 8 + t4 * 2 + e;
                    int jg = kc * 64 + jl;
                    float val = sc[nt][half * 2 + e] + slope * (float)jg;
                    if (diag && jg > ig) val -= 1e9f;
                    sc[nt][half * 2 + e] = val;
                    mx = fmaxf(mx, val);
                }
            }
            mx = fmaxf(mx, __shfl_xor_sync(0xffffffffu, mx, 1));
            mx = fmaxf(mx, __shfl_xor_sync(0xffffffffu, mx, 2));
            float mnew = fmaxf(mrow[half], mx);
            float corr = __expf(mrow[half] - mnew);
            mrow[half] = mnew;
            float rs = 0.f;
            #pragma unroll
            for (int nt = 0; nt < 8; nt++) {
                #pragma unroll
                for (int e = 0; e < 2; e++) {
                    float p = __expf(sc[nt][half * 2 + e] - mnew);
                    rs += p;
                    Ps[wr * ASTR + nt * 8 + t4 * 2 + e] = tf32r(p);
                }
            }
            rs += __shfl_xor_sync(0xffffffffu, rs, 1);
            rs += __shfl_xor_sync(0xffffffffu, rs, 2);
            lrow[half] = lrow[half] * corr + rs;
            #pragma unroll
            for (int dt = 0; dt < 8; dt++) {
                oacc[dt][half * 2]     *= corr;
                oacc[dt][half * 2 + 1] *= corr;
            }
        }
        __syncwarp();

        // O += P V : P a-frags via 8 LDSM4; V b-frags 4 LDSM4 per dt
        uint32_t pa[8][4];
        #pragma unroll
        for (int kk = 0; kk < 8; kk++)
            LDSM4(pa[kk], sPs + pfrag + kk * 32);
        #pragma unroll
        for (int dt = 0; dt < 8; dt++) {
            const uint32_t vb_ = sVs + bfrag + dt * (8 * ASTR * 4);
            uint32_t v0[4], v1[4], v2[4], v3[4];
            LDSM4(v0, vb_);
            LDSM4(v1, vb_ + 64);
            LDSM4(v2, vb_ + 128);
            LDSM4(v3, vb_ + 192);
            MMA_TF32(oacc[dt], pa[0], v0[0], v0[1]);
            MMA_TF32(oacc[dt], pa[1], v0[2], v0[3]);
            MMA_TF32(oacc[dt], pa[2], v1[0], v1[1]);
            MMA_TF32(oacc[dt], pa[3], v1[2], v1[3]);
            MMA_TF32(oacc[dt], pa[4], v2[0], v2[1]);
            MMA_TF32(oacc[dt], pa[5], v2[2], v2[3]);
            MMA_TF32(oacc[dt], pa[6], v3[0], v3[1]);
            MMA_TF32(oacc[dt], pa[7], v3[2], v3[3]);
        }
        __syncthreads();
    }

    // epilogue: write fp32 o to [B,S,H*DK]
    #pragma unroll
    for (int half = 0; half < 2; half++) {
        const int sg = qc * 64 + w * 16 + g4 + half * 8;
        const float inv = 1.0f / lrow[half];
        const size_t base = (size_t)(b * NS + sg) * (NH * NDK) + h * NDK;
        #pragma unroll
        for (int dt = 0; dt < 8; dt++) {
            int d = dt * 8 + t4 * 2;
            float v0 = oacc[dt][half * 2]     * inv;
            float v1 = oacc[dt][half * 2 + 1] * inv;
            *(float2*)&o[base + d] = make_float2(v0, v1);
        }
    }
}

// ---------------- launcher ----------------------------------------------------
extern "C" void kernel_launch(void* const* d_in, const int* in_sizes, int n_in,
                              void* d_out, int out_size)
{
    const float* z   = (const float*)d_in[0];
    const float* r   = (const float*)d_in[1];
    const float* dwn = (const float*)d_in[2];
    const float* dbn = (const float*)d_in[3];
    const float* lng = (const float*)d_in[4];
    const float* lnb = (const float*)d_in[5];
    const float* wq  = (const float*)d_in[6];
    const float* bq  = (const float*)d_in[7];
    const float* wk  = (const float*)d_in[8];
    const float* bk  = (const float*)d_in[9];
    const float* wv  = (const float*)d_in[10];
    const float* bv  = (const float*)d_in[11];
    const float* wo  = (const float*)d_in[12];
    const float* bo  = (const float*)d_in[13];
    const float* dcw = (const float*)d_in[14];
    const float* dcb = (const float*)d_in[15];
    float* out = (float*)d_out;

    float *xcat, *x, *xn, *q, *k, *v, *o;
    float *wd, *wqr, *wkr, *wvr, *wc, *cadd;
    cudaGetSymbolAddress((void**)&xcat, g_xcat);
    cudaGetSymbolAddress((void**)&x,    g_x);
    cudaGetSymbolAddress((void**)&xn,   g_xn);
    cudaGetSymbolAddress((void**)&q,    g_q);
    cudaGetSymbolAddress((void**)&k,    g_k);
    cudaGetSymbolAddress((void**)&v,    g_v);
    cudaGetSymbolAddress((void**)&o,    g_o);
    cudaGetSymbolAddress((void**)&wd,   g_wd);
    cudaGetSymbolAddress((void**)&wqr,  g_wqr);
    cudaGetSymbolAddress((void**)&wkr,  g_wkr);
    cudaGetSymbolAddress((void**)&wvr,  g_wvr);
    cudaGetSymbolAddress((void**)&wc,   g_wc);
    cudaGetSymbolAddress((void**)&cadd, g_cadd);

    cudaFuncSetAttribute(gemm_tf32<0>, cudaFuncAttributeMaxDynamicSharedMemorySize, GEMM_SMEM);
    cudaFuncSetAttribute(gemm_tf32<1>, cudaFuncAttributeMaxDynamicSharedMemorySize, GEMM_SMEM);
    cudaFuncSetAttribute(attn_tc,      cudaFuncAttributeMaxDynamicSharedMemorySize, ATTN_SMEM);

    const int WELTS = FDEC * KP;
    concat_k<<<(MROWS * KP + 255) / 256, 256>>>(r, z, xcat);
    roundpad_k<<<(WELTS + 255) / 256, 256>>>(dwn, KINR, wd);
    roundpad_k<<<(WELTS + 255) / 256, 256>>>(wq, FDEC, wqr);
    roundpad_k<<<(WELTS + 255) / 256, 256>>>(wk, FDEC, wkr);
    roundpad_k<<<(WELTS + 255) / 256, 256>>>(wv, FDEC, wvr);
    wcomb_k<<<64, 256>>>(dcw, wo, wc);
    cvec_k<<<1, 512>>>(dcw, bo, dcb, cadd);

    dim3 ggrid(8, 64);
    gemm_tf32<0><<<ggrid, 256, GEMM_SMEM>>>(xcat, wd, dbn, x);
    ln_k<<<MROWS, 256>>>(x, lng, lnb, xn);
    gemm_tf32<1><<<ggrid, 256, GEMM_SMEM>>>(xn, wqr, bq, q);
    gemm_tf32<1><<<ggrid, 256, GEMM_SMEM>>>(xn, wkr, bk, k);
    gemm_tf32<1><<<ggrid, 256, GEMM_SMEM>>>(xn, wvr, bv, v);
    attn_tc<<<dim3(NS / 64, NH, NB), 128, ATTN_SMEM>>>(q, k, v, o);
    dec2_k<<<MROWS, 512>>>(x, o, dcw, wc, cadd, out);
}

// round 14
// speedup vs baseline: 1.1435x; 1.0563x over previous
#include <cuda_runtime.h>
#include <cuda_bf16.h>
#include <cstdint>
#include <math.h>

// Problem dims (fixed)
#define NB   8
#define NS   1024
#define NH   16
#define NDK  64
#define FDEC 1024
#define FD   16
#define KINR 784
#define KP   1024
#define MROWS (NB*NS)   // 8192

// ---------------- scratch (static __device__, no allocation) ----------------
__device__ float g_xcat[MROWS * KP];     // concat input, tf32-rounded
__device__ float g_x   [MROWS * FDEC];   // dense output (residual, fp32)
__device__ float g_xn  [MROWS * FDEC];   // LN output, tf32-rounded
__device__ float g_q   [MROWS * FDEC];   // tf32-rounded
__device__ float g_k   [MROWS * FDEC];   // tf32-rounded
__device__ float g_v   [MROWS * FDEC];   // tf32-rounded
__device__ float g_o   [MROWS * FDEC];   // attention out, fp32
__device__ float g_wd  [FDEC * KP];
__device__ float g_wqr [FDEC * KP];
__device__ float g_wkr [FDEC * KP];
__device__ float g_wvr [FDEC * KP];
__device__ float g_wc  [FD * FDEC];      // dcw @ wo
__device__ float g_cadd[FD];             // dcw . bo + dec_b

// ---------------- PTX helpers ------------------------------------------------
__device__ __forceinline__ uint32_t smem_u32(const void* p) {
    uint32_t a;
    asm("{ .reg .u64 t; cvta.to.shared.u64 t, %1; cvt.u32.u64 %0, t; }" : "=r"(a) : "l"(p));
    return a;
}

#define LDSM4(R, A) \
    asm volatile("ldmatrix.sync.aligned.m8n8.x4.shared.b16 {%0,%1,%2,%3}, [%4];" \
        : "=r"((R)[0]), "=r"((R)[1]), "=r"((R)[2]), "=r"((R)[3]) : "r"(A))

#define MMA_TF32(C, A, B0, B1) \
    asm volatile("mma.sync.aligned.m16n8k8.row.col.f32.tf32.tf32.f32 " \
        "{%0,%1,%2,%3},{%4,%5,%6,%7},{%8,%9},{%0,%1,%2,%3};" \
        : "+f"((C)[0]), "+f"((C)[1]), "+f"((C)[2]), "+f"((C)[3]) \
        : "r"((A)[0]), "r"((A)[1]), "r"((A)[2]), "r"((A)[3]), "r"(B0), "r"(B1))

__device__ __forceinline__ uint32_t to_tf32(float f) {
    uint32_t r;
    asm("cvt.rna.tf32.f32 %0, %1;" : "=r"(r) : "f"(f));
    return r;
}
__device__ __forceinline__ float tf32r(float f) {
    return __uint_as_float(to_tf32(f));
}

__device__ __forceinline__ void cpa16(uint32_t dst, const void* src) {
    asm volatile("cp.async.cg.shared.global [%0], [%1], 16;" :: "r"(dst), "l"(src));
}
#define CP_COMMIT() asm volatile("cp.async.commit_group;" ::: "memory")
#define CP_WAIT(n)  asm volatile("cp.async.wait_group %0;" :: "n"(n) : "memory")

// ---------------- producers (tf32-rounded outputs) ---------------------------
__global__ void __launch_bounds__(256) concat_k(
    const float* __restrict__ r, const float* __restrict__ z,
    float* __restrict__ xcat)
{
    int idx = blockIdx.x * 256 + threadIdx.x;
    if (idx >= MROWS * KP) return;
    int m = idx >> 10, f = idx & 1023;
    float v = (f < 16) ? r[m * 16 + f]
            : (f < KINR) ? z[(m >> 10) * 768 + (f - 16)] : 0.f;
    xcat[idx] = tf32r(v);
}

__global__ void __launch_bounds__(256) roundpad_k(
    const float* __restrict__ w, int Ksrc, float* __restrict__ dst)
{
    int idx = blockIdx.x * 256 + threadIdx.x;
    if (idx >= FDEC * KP) return;
    int n = idx >> 10, k = idx & 1023;
    dst[idx] = (k < Ksrc) ? tf32r(w[n * Ksrc + k]) : 0.f;
}

// wc[n][c] = sum_j dcw[n][j] * wo[j][c]   (16 x 1024), exact fp32
__global__ void __launch_bounds__(256) wcomb_k(
    const float* __restrict__ dcw, const float* __restrict__ wo,
    float* __restrict__ wc)
{
    const int n = threadIdx.x >> 4;
    const int c = blockIdx.x * 16 + (threadIdx.x & 15);
    const float* dr = dcw + n * FDEC;
    float acc = 0.f;
    #pragma unroll 8
    for (int j = 0; j < FDEC; j++)
        acc += dr[j] * wo[(size_t)j * FDEC + c];
    wc[n * FDEC + c] = acc;
}

__global__ void __launch_bounds__(512) cvec_k(
    const float* __restrict__ dcw, const float* __restrict__ bo,
    const float* __restrict__ dcb, float* __restrict__ cadd)
{
    const int n = threadIdx.x >> 5, lane = threadIdx.x & 31;
    float sum = 0.f;
    #pragma unroll
    for (int i = 0; i < 8; i++) {
        float4 a = ((const float4*)(dcw + n * FDEC))[lane + i * 32];
        float4 b = ((const float4*)bo)[lane + i * 32];
        sum += a.x * b.x + a.y * b.y + a.z * b.z + a.w * b.w;
    }
    #pragma unroll
    for (int o = 16; o; o >>= 1) sum += __shfl_xor_sync(0xffffffffu, sum, o);
    if (lane == 0) cadd[n] = sum + dcb[n];
}

// ---------------- LayerNorm (fp32 in, tf32-rounded out) ----------------------
__device__ __forceinline__ float blockReduce(float val, float* sh)
{
    __syncthreads();
    int lane = threadIdx.x & 31, wid = threadIdx.x >> 5;
    #pragma unroll
    for (int o = 16; o; o >>= 1) val += __shfl_xor_sync(0xffffffffu, val, o);
    if (lane == 0) sh[wid] = val;
    __syncthreads();
    if (wid == 0) {
        val = (lane < 8) ? sh[lane] : 0.f;
        #pragma unroll
        for (int o = 4; o; o >>= 1) val += __shfl_xor_sync(0xffffffffu, val, o);
        if (lane == 0) sh[0] = val;
    }
    __syncthreads();
    return sh[0];
}

__global__ void __launch_bounds__(256) ln_k(
    const float* __restrict__ x, const float* __restrict__ g,
    const float* __restrict__ beta, float* __restrict__ xn)
{
    __shared__ float red[32];
    int row = blockIdx.x;
    float4 v = ((const float4*)(x + (size_t)row * 1024))[threadIdx.x];
    float s = blockReduce(v.x + v.y + v.z + v.w, red);
    float mean = s * (1.0f / 1024.0f);
    float dx = v.x - mean, dy = v.y - mean, dz = v.z - mean, dw = v.w - mean;
    float s2 = blockReduce(dx*dx + dy*dy + dz*dz + dw*dw, red);
    float inv = rsqrtf(s2 * (1.0f / 1024.0f) + 1e-6f);
    float4 gg = ((const float4*)g)[threadIdx.x];
    float4 bb = ((const float4*)beta)[threadIdx.x];
    float4 o;
    o.x = tf32r(gg.x * dx * inv + bb.x);
    o.y = tf32r(gg.y * dy * inv + bb.y);
    o.z = tf32r(gg.z * dz * inv + bb.z);
    o.w = tf32r(gg.w * dw * inv + bb.w);
    ((float4*)(xn + (size_t)row * 1024))[threadIdx.x] = o;
}

// ---------------- tf32 mma GEMM with ldmatrix fragments ----------------------
// MODE 0: plain fp32 store; MODE 1: qkv scatter [B,H,S,DK], tf32-rounded.
#define GSTR  36
#define TILE_BYTES (128 * GSTR * 4)
#define STAGE_B (2 * TILE_BYTES)
#define GEMM_SMEM (3 * STAGE_B)

template<int MODE>
__global__ void __launch_bounds__(256) gemm_tf32(
    const float* __restrict__ A, const float* __restrict__ Bw,
    const float* __restrict__ bias, float* __restrict__ C)
{
    extern __shared__ char sm[];
    const uint32_t sbase = smem_u32(sm);
    const int tid = threadIdx.x, lane = tid & 31, wid = tid >> 5;
    const int g4 = lane >> 2, t4 = lane & 3;
    const int bm = blockIdx.y * 128, bn = blockIdx.x * 128;
    const int wm = (wid & 3) * 32, wn = (wid >> 2) * 64;

    float acc[2][8][4];
    #pragma unroll
    for (int a = 0; a < 2; a++)
        #pragma unroll
        for (int b = 0; b < 8; b++)
            #pragma unroll
            for (int c = 0; c < 4; c++) acc[a][b][c] = 0.f;

    const uint32_t aoff =
        ((uint32_t)(wm + (lane & 7) + ((lane >> 3) & 1) * 8) * GSTR
         + ((lane >> 4) << 2)) * 4;
    const uint32_t boff =
        ((uint32_t)(wn + (lane & 7)) * GSTR + ((lane >> 3) & 3) * 4) * 4;

    auto load_stage = [&](int slot, int k0) {
        const uint32_t sa = sbase + slot * STAGE_B;
        #pragma unroll
        for (int c = 0; c < 4; c++) {
            int chunk = tid + c * 256;
            int row = chunk >> 3, seg = chunk & 7;
            cpa16(sa + row * (GSTR*4) + seg * 16,
                  A + (size_t)(bm + row) * KP + k0 + seg * 4);
        }
        const uint32_t sb = sa + TILE_BYTES;
        #pragma unroll
        for (int c = 0; c < 4; c++) {
            int chunk = tid + c * 256;
            int row = chunk >> 3, seg = chunk & 7;
            cpa16(sb + row * (GSTR*4) + seg * 16,
                  Bw + (size_t)(bn + row) * KP + k0 + seg * 4);
        }
    };

    load_stage(0, 0);  CP_COMMIT();
    load_stage(1, 32); CP_COMMIT();

    for (int i = 0; i < 32; i++) {
        if (i < 31) { CP_WAIT(1); } else { CP_WAIT(0); }
        __syncthreads();
        if (i + 2 < 32) { load_stage((i + 2) % 3, (i + 2) * 32); CP_COMMIT(); }

        const uint32_t As = sbase + (i % 3) * STAGE_B;
        const uint32_t Bs = As + TILE_BYTES;

        uint32_t a[4][2][4];
        #pragma unroll
        for (int kk = 0; kk < 4; kk++)
            #pragma unroll
            for (int am = 0; am < 2; am++)
                LDSM4(a[kk][am], As + aoff + am * (16 * GSTR * 4) + kk * 32);

        #pragma unroll
        for (int nt = 0; nt < 8; nt++) {
            uint32_t b01[4], b23[4];
            const uint32_t bb = Bs + boff + nt * (8 * GSTR * 4);
            LDSM4(b01, bb);
            LDSM4(b23, bb + 64);
            MMA_TF32(acc[0][nt], a[0][0], b01[0], b01[1]);
            MMA_TF32(acc[1][nt], a[0][1], b01[0], b01[1]);
            MMA_TF32(acc[0][nt], a[1][0], b01[2], b01[3]);
            MMA_TF32(acc[1][nt], a[1][1], b01[2], b01[3]);
            MMA_TF32(acc[0][nt], a[2][0], b23[0], b23[1]);
            MMA_TF32(acc[1][nt], a[2][1], b23[0], b23[1]);
            MMA_TF32(acc[0][nt], a[3][0], b23[2], b23[3]);
            MMA_TF32(acc[1][nt], a[3][1], b23[2], b23[3]);
        }
    }

    #pragma unroll
    for (int am = 0; am < 2; am++) {
        #pragma unroll
        for (int nt = 0; nt < 8; nt++) {
            int mrow = bm + wm + am * 16 + g4;
            int ncol = bn + wn + nt * 8 + t4 * 2;
            float b0 = bias[ncol], b1 = bias[ncol + 1];
            #pragma unroll
            for (int r = 0; r < 2; r++) {
                int m = mrow + r * 8;
                float v0 = acc[am][nt][r * 2]     + b0;
                float v1 = acc[am][nt][r * 2 + 1] + b1;
                if (MODE == 0) {
                    *(float2*)&C[(size_t)m * 1024 + ncol] = make_float2(v0, v1);
                } else {
                    int bb = m >> 10, s = m & 1023, h = ncol >> 6, d = ncol & 63;
                    *(float2*)&C[(size_t)(((bb << 4) + h) * 1024 + s) * 64 + d] =
                        make_float2(tf32r(v0), tf32r(v1));
                }
            }
        }
    }
}

// ---------------- fused decode: out = x.dw + o.wc + cadd, transposed ---------
__global__ void __launch_bounds__(512) dec2_k(
    const float* __restrict__ x, const float* __restrict__ o,
    const float* __restrict__ dw, const float* __restrict__ wc,
    const float* __restrict__ cadd, float* __restrict__ out)
{
    const int m = blockIdx.x;
    const int b = m >> 10, s = m & 1023;
    const int n = threadIdx.x >> 5;
    const int lane = threadIdx.x & 31;
    const float4* xr = (const float4*)(x  + (size_t)m * FDEC);
    const float4* orr = (const float4*)(o + (size_t)m * FDEC);
    const float4* wr = (const float4*)(dw + (size_t)n * FDEC);
    const float4* cr = (const float4*)(wc + (size_t)n * FDEC);
    float sum = 0.f;
    #pragma unroll
    for (int i = 0; i < 8; i++) {
        float4 a = xr[lane + i * 32];
        float4 w = wr[lane + i * 32];
        float4 oo = orr[lane + i * 32];
        float4 c = cr[lane + i * 32];
        sum += a.x * w.x + a.y * w.y + a.z * w.z + a.w * w.w;
        sum += oo.x * c.x + oo.y * c.y + oo.z * c.z + oo.w * c.w;
    }
    #pragma unroll
    for (int oo = 16; oo; oo >>= 1) sum += __shfl_xor_sync(0xffffffffu, sum, oo);
    if (lane == 0)
        out[(size_t)(b * FD + n) * NS + s] = sum + cadd[n];
}

// ---------------- tf32 mma flash attention, 128-row q-chunks -----------------
// 256 threads (8 warps x 16 q-rows), KV tiles of 64. Q in smem (scaled, loaded
// once); all fragments via ldmatrix.x4 on f32-as-b16 tiles. Warps 0-3 skip the
// fully-masked final tile.
#define ASTR 68
#define ATTN_SMEM ((128 + 64 + 64 + 128) * ASTR * (int)sizeof(float))  // 104448

__global__ void __launch_bounds__(256) attn_tc(
    const float* __restrict__ q, const float* __restrict__ k,
    const float* __restrict__ v, float* __restrict__ o)
{
    extern __shared__ float smf[];
    float* Qs = smf;                   // [128][68] scaled Q
    float* Ks = Qs + 128 * ASTR;       // [64][68]  K[j][d]
    float* Vs = Ks + 64 * ASTR;        // [64][68]  V^T: Vs[d][j]
    float* Ps = Vs + 64 * ASTR;        // [128][68] P, tf32-rounded

    const int qc = blockIdx.x, h = blockIdx.y, b = blockIdx.z;
    const int tid = threadIdx.x, lane = tid & 31, w = tid >> 5;
    const int g4 = lane >> 2, t4 = lane & 3;

    const uint32_t sQs = smem_u32(Qs), sKs = smem_u32(Ks);
    const uint32_t sVs = smem_u32(Vs), sPs = smem_u32(Ps);

    const size_t head = (size_t)(b * NH + h) * NS * NDK;
    const float* qb = q + head;
    const float* kb = k + head;
    const float* vb = v + head;

    // load Q chunk (128 rows), scaled by 0.125 (exact on tf32 values)
    {
        const int row = tid >> 1, col0 = (tid & 1) * 32;
        const float* src = qb + (size_t)(qc * 128 + row) * 64 + col0;
        float* dst = Qs + row * ASTR + col0;
        #pragma unroll
        for (int c = 0; c < 32; c += 4) {
            float4 t = *(const float4*)(src + c);
            t.x *= 0.125f; t.y *= 0.125f; t.z *= 0.125f; t.w *= 0.125f;
            *(float4*)(dst + c) = t;
        }
    }

    // fragment offsets
    const uint32_t bfrag = ((uint32_t)(lane & 7) * ASTR + ((lane >> 3) & 3) * 4) * 4;
    const uint32_t afrag =
        ((uint32_t)(w * 16 + (lane & 7) + ((lane >> 3) & 1) * 8) * ASTR
         + ((lane >> 4) << 2)) * 4;

    const float slope = exp2f(-0.5f * (float)(h + 1));
    float oacc[8][4];
    #pragma unroll
    for (int dt = 0; dt < 8; dt++)
        #pragma unroll
        for (int c = 0; c < 4; c++) oacc[dt][c] = 0.f;
    float mrow[2] = { -1e30f, -1e30f };
    float lrow[2] = { 0.f, 0.f };

    const int lrow_ld = tid >> 2, lcol0 = (tid & 3) * 16;   // KV tile loads
    const int kmax = 2 * qc + 1;

    __syncthreads();   // Qs ready

    for (int kc = 0; kc <= kmax; kc++) {
        // load K [j][d]; V transposed [d][j]  (256 threads, 16 floats each)
        {
            const float* ksrc = kb + (size_t)(kc * 64 + lrow_ld) * 64 + lcol0;
            const float* vsrc = vb + (size_t)(kc * 64 + lrow_ld) * 64 + lcol0;
            float* kd = Ks + lrow_ld * ASTR + lcol0;
            #pragma unroll
            for (int c = 0; c < 16; c += 4) {
                float4 t = *(const float4*)(ksrc + c);
                *(float4*)(kd + c) = t;
                float4 tv = *(const float4*)(vsrc + c);
                Vs[(lcol0 + c + 0) * ASTR + lrow_ld] = tv.x;
                Vs[(lcol0 + c + 1) * ASTR + lrow_ld] = tv.y;
                Vs[(lcol0 + c + 2) * ASTR + lrow_ld] = tv.z;
                Vs[(lcol0 + c + 3) * ASTR + lrow_ld] = tv.w;
            }
        }
        __syncthreads();

        const bool active = !(kc == kmax && w < 4);   // rows 0-63 fully masked on last tile
        if (active) {
            // Q a-fragments for this warp's 16 rows
            uint32_t qa[8][4];
            #pragma unroll
            for (int kk = 0; kk < 8; kk++)
                LDSM4(qa[kk], sQs + afrag + kk * 32);

            // S = Q K^T
            float sc[8][4];
            #pragma unroll
            for (int nt = 0; nt < 8; nt++) {
                sc[nt][0] = sc[nt][1] = sc[nt][2] = sc[nt][3] = 0.f;
                const uint32_t kb_ = sKs + bfrag + nt * (8 * ASTR * 4);
                uint32_t b0[4], b1[4], b2[4], b3[4];
                LDSM4(b0, kb_);
                LDSM4(b1, kb_ + 64);
                LDSM4(b2, kb_ + 128);
                LDSM4(b3, kb_ + 192);
                MMA_TF32(sc[nt], qa[0], b0[0], b0[1]);
                MMA_TF32(sc[nt], qa[1], b0[2], b0[3]);
                MMA_TF32(sc[nt], qa[2], b1[0], b1[1]);
                MMA_TF32(sc[nt], qa[3], b1[2], b1[3]);
                MMA_TF32(sc[nt], qa[4], b2[0], b2[1]);
                MMA_TF32(sc[nt], qa[5], b2[2], b2[3]);
                MMA_TF32(sc[nt], qa[6], b3[0], b3[1]);
                MMA_TF32(sc[nt], qa[7], b3[2], b3[3]);
            }

            // softmax; Ps written tf32-rounded
            const bool diag = (kc >= 2 * qc);
            #pragma unroll
            for (int half = 0; half < 2; half++) {
                const int wr = w * 16 + g4 + half * 8;
                const int ig = qc * 128 + wr;
                float mx = -1e30f;
                #pragma unroll
                for (int nt = 0; nt < 8; nt++) {
                    #pragma unroll
                    for (int e = 0; e < 2; e++) {
                        int jg = kc * 64 + nt * 8 + t4 * 2 + e;
                        float val = sc[nt][half * 2 + e] + slope * (float)jg;
                        if (diag && jg > ig) val -= 1e9f;
                        sc[nt][half * 2 + e] = val;
                        mx = fmaxf(mx, val);
                    }
                }
                mx = fmaxf(mx, __shfl_xor_sync(0xffffffffu, mx, 1));
                mx = fmaxf(mx, __shfl_xor_sync(0xffffffffu, mx, 2));
                float mnew = fmaxf(mrow[half], mx);
                float corr = __expf(mrow[half] - mnew);
                mrow[half] = mnew;
                float rs = 0.f;
                #pragma unroll
                for (int nt = 0; nt < 8; nt++) {
                    #pragma unroll
                    for (int e = 0; e < 2; e++) {
                        float p = __expf(sc[nt][half * 2 + e] - mnew);
                        rs += p;
                        Ps[wr * ASTR + nt * 8 + t4 * 2 + e] = tf32r(p);
                    }
                }
                rs += __shfl_xor_sync(0xffffffffu, rs, 1);
                rs += __shfl_xor_sync(0xffffffffu, rs, 2);
                lrow[half] = lrow[half] * corr + rs;
                #pragma unroll
                for (int dt = 0; dt < 8; dt++) {
                    oacc[dt][half * 2]     *= corr;
                    oacc[dt][half * 2 + 1] *= corr;
                }
            }
            __syncwarp();

            // O += P V
            uint32_t pa[8][4];
            #pragma unroll
            for (int kk = 0; kk < 8; kk++)
                LDSM4(pa[kk], sPs + afrag + kk * 32);
            #pragma unroll
            for (int dt = 0; dt < 8; dt++) {
                const uint32_t vb_ = sVs + bfrag + dt * (8 * ASTR * 4);
                uint32_t v0[4], v1[4], v2[4], v3[4];
                LDSM4(v0, vb_);
                LDSM4(v1, vb_ + 64);
                LDSM4(v2, vb_ + 128);
                LDSM4(v3, vb_ + 192);
                MMA_TF32(oacc[dt], pa[0], v0[0], v0[1]);
                MMA_TF32(oacc[dt], pa[1], v0[2], v0[3]);
                MMA_TF32(oacc[dt], pa[2], v1[0], v1[1]);
                MMA_TF32(oacc[dt], pa[3], v1[2], v1[3]);
                MMA_TF32(oacc[dt], pa[4], v2[0], v2[1]);
                MMA_TF32(oacc[dt], pa[5], v2[2], v2[3]);
                MMA_TF32(oacc[dt], pa[6], v3[0], v3[1]);
                MMA_TF32(oacc[dt], pa[7], v3[2], v3[3]);
            }
        }
        __syncthreads();
    }

    // epilogue: write fp32 o to [B,S,H*DK]
    #pragma unroll
    for (int half = 0; half < 2; half++) {
        const int sg = qc * 128 + w * 16 + g4 + half * 8;
        const float inv = 1.0f / lrow[half];
        const size_t base = (size_t)(b * NS + sg) * (NH * NDK) + h * NDK;
        #pragma unroll
        for (int dt = 0; dt < 8; dt++) {
            int d = dt * 8 + t4 * 2;
            float v0 = oacc[dt][half * 2]     * inv;
            float v1 = oacc[dt][half * 2 + 1] * inv;
            *(float2*)&o[base + d] = make_float2(v0, v1);
        }
    }
}

// ---------------- launcher ----------------------------------------------------
extern "C" void kernel_launch(void* const* d_in, const int* in_sizes, int n_in,
                              void* d_out, int out_size)
{
    const float* z   = (const float*)d_in[0];
    const float* r   = (const float*)d_in[1];
    const float* dwn = (const float*)d_in[2];
    const float* dbn = (const float*)d_in[3];
    const float* lng = (const float*)d_in[4];
    const float* lnb = (const float*)d_in[5];
    const float* wq  = (const float*)d_in[6];
    const float* bq  = (const float*)d_in[7];
    const float* wk  = (const float*)d_in[8];
    const float* bk  = (const float*)d_in[9];
    const float* wv  = (const float*)d_in[10];
    const float* bv  = (const float*)d_in[11];
    const float* wo  = (const float*)d_in[12];
    const float* bo  = (const float*)d_in[13];
    const float* dcw = (const float*)d_in[14];
    const float* dcb = (const float*)d_in[15];
    float* out = (float*)d_out;

    float *xcat, *x, *xn, *q, *k, *v, *o;
    float *wd, *wqr, *wkr, *wvr, *wc, *cadd;
    cudaGetSymbolAddress((void**)&xcat, g_xcat);
    cudaGetSymbolAddress((void**)&x,    g_x);
    cudaGetSymbolAddress((void**)&xn,   g_xn);
    cudaGetSymbolAddress((void**)&q,    g_q);
    cudaGetSymbolAddress((void**)&k,    g_k);
    cudaGetSymbolAddress((void**)&v,    g_v);
    cudaGetSymbolAddress((void**)&o,    g_o);
    cudaGetSymbolAddress((void**)&wd,   g_wd);
    cudaGetSymbolAddress((void**)&wqr,  g_wqr);
    cudaGetSymbolAddress((void**)&wkr,  g_wkr);
    cudaGetSymbolAddress((void**)&wvr,  g_wvr);
    cudaGetSymbolAddress((void**)&wc,   g_wc);
    cudaGetSymbolAddress((void**)&cadd, g_cadd);

    cudaFuncSetAttribute(gemm_tf32<0>, cudaFuncAttributeMaxDynamicSharedMemorySize, GEMM_SMEM);
    cudaFuncSetAttribute(gemm_tf32<1>, cudaFuncAttributeMaxDynamicSharedMemorySize, GEMM_SMEM);
    cudaFuncSetAttribute(attn_tc,      cudaFuncAttributeMaxDynamicSharedMemorySize, ATTN_SMEM);

    const int WELTS = FDEC * KP;
    concat_k<<<(MROWS * KP + 255) / 256, 256>>>(r, z, xcat);
    roundpad_k<<<(WELTS + 255) / 256, 256>>>(dwn, KINR, wd);
    roundpad_k<<<(WELTS + 255) / 256, 256>>>(wq, FDEC, wqr);
    roundpad_k<<<(WELTS + 255) / 256, 256>>>(wk, FDEC, wkr);
    roundpad_k<<<(WELTS + 255) / 256, 256>>>(wv, FDEC, wvr);
    wcomb_k<<<64, 256>>>(dcw, wo, wc);
    cvec_k<<<1, 512>>>(dcw, bo, dcb, cadd);

    dim3 ggrid(8, 64);
    gemm_tf32<0><<<ggrid, 256, GEMM_SMEM>>>(xcat, wd, dbn, x);
    ln_k<<<MROWS, 256>>>(x, lng, lnb, xn);
    gemm_tf32<1><<<ggrid, 256, GEMM_SMEM>>>(xn, wqr, bq, q);
    gemm_tf32<1><<<ggrid, 256, GEMM_SMEM>>>(xn, wkr, bk, k);
    gemm_tf32<1><<<ggrid, 256, GEMM_SMEM>>>(xn, wvr, bv, v);
    attn_tc<<<dim3(NS / 128, NH, NB), 256, ATTN_SMEM>>>(q, k, v, o);
    dec2_k<<<MROWS, 512>>>(x, o, dcw, wc, cadd, out);
}